// round 8
// baseline (speedup 1.0000x reference)
#include <cuda_runtime.h>
#include <math.h>

#define BATCH 4
#define NPTS  8192
#define KNB   16
#define NPOS  (BATCH*NPTS*KNB)   // 524288
#define NQ    (BATCH*NPTS)       // 32768
#define CAP   48
#define NPART 4

__device__ int g_idx[NQ*KNB];
__device__ unsigned long long g_sbuf[(long long)NQ*NPART*CAP];
__device__ int g_scnt[NQ*NPART];

typedef unsigned long long u64;

__device__ __forceinline__ u64 pk2(float x, float y) {
    u64 r; asm("mov.b64 %0,{%1,%2};" : "=l"(r) : "f"(x), "f"(y)); return r;
}
__device__ __forceinline__ float2 up2(u64 v) {
    float2 r; asm("mov.b64 {%0,%1},%2;" : "=f"(r.x), "=f"(r.y) : "l"(v)); return r;
}
__device__ __forceinline__ void fma2(u64& d, u64 a, u64 b) {
    asm("fma.rn.f32x2 %0,%1,%2,%0;" : "+l"(d) : "l"(a), "l"(b));
}
__device__ __forceinline__ float leaky(float v) { return v >= 0.f ? v : 0.2f*v; }

// =====================================================================
// KNN part 1 (unchanged from R6): branchless 2-pass top-16 per quarter
// =====================================================================
__global__ __launch_bounds__(128) void knn_part(const float* __restrict__ xyz)
{
    extern __shared__ float4 tile[];
    const int tid = threadIdx.x;
    const int quarter = blockIdx.x & 3;
    const int qb = (blockIdx.x >> 2) & 63;
    const int b  = blockIdx.x >> 8;
    const int i  = qb*128 + tid;
    const float* xb = xyz + b*3*NPTS;
    const int c0 = quarter*2048;

    for (int l = tid; l < 512; l += 128) {
        float4 vx = ((const float4*)(xb + c0))[l];
        float4 vy = ((const float4*)(xb + NPTS + c0))[l];
        float4 vz = ((const float4*)(xb + 2*NPTS + c0))[l];
        tile[4*l+0] = make_float4(vx.x, vy.x, vz.x, fmaf(vx.x,vx.x, fmaf(vy.x,vy.x, vz.x*vz.x)));
        tile[4*l+1] = make_float4(vx.y, vy.y, vz.y, fmaf(vx.y,vx.y, fmaf(vy.y,vy.y, vz.y*vz.y)));
        tile[4*l+2] = make_float4(vx.z, vy.z, vz.z, fmaf(vx.z,vx.z, fmaf(vy.z,vy.z, vz.z*vz.z)));
        tile[4*l+3] = make_float4(vx.w, vy.w, vz.w, fmaf(vx.w,vx.w, fmaf(vy.w,vy.w, vz.w*vz.w)));
    }
    __syncthreads();

    const float x2 = -2.0f*xb[i], y2 = -2.0f*xb[NPTS+i], z2 = -2.0f*xb[2*NPTS+i];

    float s[32];
#pragma unroll
    for (int t = 0; t < 32; t++) s[t] = 3.4e38f;
    for (int j0 = 0; j0 < 2048; j0 += 32) {
#pragma unroll
        for (int u = 0; u < 32; u++) {
            float4 p = tile[j0+u];
            float d = fmaf(x2, p.x, fmaf(y2, p.y, fmaf(z2, p.z, p.w)));
            s[u] = fminf(s[u], d);
        }
    }

#pragma unroll
    for (int k = 2; k <= 32; k <<= 1) {
#pragma unroll
        for (int j = k >> 1; j > 0; j >>= 1) {
#pragma unroll
            for (int ii = 0; ii < 32; ii++) {
                int l = ii ^ j;
                if (l > ii) {
                    float lo = fminf(s[ii], s[l]);
                    float hi = fmaxf(s[ii], s[l]);
                    bool up = ((ii & k) == 0);
                    s[ii] = up ? lo : hi;
                    s[l]  = up ? hi : lo;
                }
            }
        }
    }
    const float T = s[15];

    u64 buf[CAP];
    int cnt = 0, ovf = 0;
    for (int j = 0; j < 2048; j++) {
        float4 p = tile[j];
        float d = fmaf(x2, p.x, fmaf(y2, p.y, fmaf(z2, p.z, p.w)));
        if (d <= T) {
            if (cnt < CAP) { buf[cnt] = pk2(d, __int_as_float(c0+j)); cnt++; }
            else ovf = 1;
        }
    }

    if (ovf) {
        float bd[16]; int bj[16];
#pragma unroll
        for (int t = 0; t < 16; t++) { bd[t] = 3.4e38f; bj[t] = 0; }
        float cm = 3.4e38f;
        for (int j = 0; j < 2048; j++) {
            float4 p = tile[j];
            float d = fmaf(x2, p.x, fmaf(y2, p.y, fmaf(z2, p.z, p.w)));
            if (d < cm) {
                int am = 0; float mv = bd[0];
#pragma unroll
                for (int u = 1; u < 16; u++) if (bd[u] > mv) { mv = bd[u]; am = u; }
#pragma unroll
                for (int u = 0; u < 16; u++) if (u == am) { bd[u] = d; bj[u] = c0 + j; }
                cm = bd[0];
#pragma unroll
                for (int u = 1; u < 16; u++) cm = fmaxf(cm, bd[u]);
            }
        }
        cnt = 16;
#pragma unroll
        for (int t = 0; t < 16; t++) buf[t] = pk2(bd[t], __int_as_float(bj[t]));
    }

    const int qg = b*NPTS + i;
    g_scnt[qg*NPART + quarter] = cnt;
    u64* dst = g_sbuf + (long long)(qg*NPART + quarter)*CAP;
    for (int t = 0; t < cnt; t++) dst[t] = buf[t];
}

// =====================================================================
// KNN part 2 (unchanged)
// =====================================================================
__global__ __launch_bounds__(256) void knn_merge()
{
    const int q = blockIdx.x*256 + threadIdx.x;
    float bd[16]; int bj[16];
#pragma unroll
    for (int t = 0; t < 16; t++) { bd[t] = 3.4e38f; bj[t] = 0; }
    float cm = 3.4e38f;
#pragma unroll
    for (int h = 0; h < NPART; h++) {
        const int c = g_scnt[q*NPART + h];
        const u64* src = g_sbuf + (long long)(q*NPART + h)*CAP;
        for (int e = 0; e < c; e++) {
            float2 v = up2(src[e]);
            float d = v.x;
            if (d < cm) {
                int am = 0; float mv = bd[0];
#pragma unroll
                for (int u = 1; u < 16; u++) if (bd[u] > mv) { mv = bd[u]; am = u; }
#pragma unroll
                for (int u = 0; u < 16; u++) if (u == am) { bd[u] = d; bj[u] = __float_as_int(v.y); }
                cm = bd[0];
#pragma unroll
                for (int u = 1; u < 16; u++) cm = fmaxf(cm, bd[u]);
            }
        }
    }
#pragma unroll
    for (int t = 0; t < 16; t++) g_idx[q*16 + t] = bj[t];
}

// =====================================================================
// smem layout (floats) — fused kernel, 256 threads, 2 CTAs/SM
// =====================================================================
#define SA    0        // 4352
#define SB    4352     // 4352
#define SC    8704     // 4352
#define SW0   13056    // 4352 ping
#define SW1   17408    // 4352 pong
#define SX1   21760    // 256
#define SBIAS 22016    // 256
#define SMEM_FLOATS 22272   // 89088 B -> 2 CTAs/SM

// ---- weight loaders: LDG->regs (4 float4/thread), STS k-major ----
// A-type: 64 outs x 64 k (stride 68)
template<int KFULL>
__device__ __forceinline__ void ldgA(float4 r[4], const float* __restrict__ src,
                                     int koff, int tid)
{
#pragma unroll
    for (int it = 0; it < 4; it++) {
        int l = it*256 + tid;
        int o = l & 63, k4 = l >> 6;
        r[it] = *(const float4*)(src + o*KFULL + koff + 4*k4);
    }
}
__device__ __forceinline__ void stsA(float* __restrict__ dst, const float4 r[4], int tid)
{
#pragma unroll
    for (int it = 0; it < 4; it++) {
        int l = it*256 + tid;
        int o = l & 63, k = (l >> 6)*4;
        dst[(k  )*68+o] = r[it].x; dst[(k+1)*68+o] = r[it].y;
        dst[(k+2)*68+o] = r[it].z; dst[(k+3)*68+o] = r[it].w;
    }
}
// B-type: 128 outs x 32 k (stride 132)
template<int KFULL>
__device__ __forceinline__ void ldgB(float4 r[4], const float* __restrict__ src,
                                     int koff, int tid)
{
#pragma unroll
    for (int it = 0; it < 4; it++) {
        int l = it*256 + tid;
        int o = l & 127, k4 = l >> 7;
        r[it] = *(const float4*)(src + o*KFULL + koff + 4*k4);
    }
}
__device__ __forceinline__ void stsB(float* __restrict__ dst, const float4 r[4], int tid)
{
#pragma unroll
    for (int it = 0; it < 4; it++) {
        int l = it*256 + tid;
        int o = l & 127, k = (l >> 7)*4;
        dst[(k  )*132+o] = r[it].x; dst[(k+1)*132+o] = r[it].y;
        dst[(k+2)*132+o] = r[it].z; dst[(k+3)*132+o] = r[it].w;
    }
}

// 8 outs (4 pairs) x 4 pos, K=32. w: [k][o] stride 132.
__device__ __forceinline__ void gemmB32(const float* __restrict__ w,
                                        const float* __restrict__ a,
                                        int og, int pg, u64 acc[4][4])
{
#pragma unroll 4
    for (int k = 0; k < 32; k++) {
        const float* wr = w + k*132 + og*8;
        ulonglong2 w01 = *(const ulonglong2*)wr;
        ulonglong2 w23 = *(const ulonglong2*)(wr+4);
        u64 wp[4] = {w01.x,w01.y,w23.x,w23.y};
        float4 av = *(const float4*)(a + k*68 + pg*4);
        u64 as[4] = {pk2(av.x,av.x), pk2(av.y,av.y), pk2(av.z,av.z), pk2(av.w,av.w)};
#pragma unroll
        for (int op = 0; op < 4; op++)
#pragma unroll
            for (int p = 0; p < 4; p++) fma2(acc[op][p], wp[op], as[p]);
    }
}

// 4 outs (2 pairs) x 4 pos, K=64. w: [k][o] stride 68.
__device__ __forceinline__ void gemmA64(const float* __restrict__ w,
                                        const float* __restrict__ a,
                                        int og, int pg, u64 acc[2][4])
{
#pragma unroll 4
    for (int k = 0; k < 64; k++) {
        ulonglong2 w01 = *(const ulonglong2*)(w + k*68 + og*4);
        u64 wp[2] = {w01.x, w01.y};
        float4 av = *(const float4*)(a + k*68 + pg*4);
        u64 as[4] = {pk2(av.x,av.x), pk2(av.y,av.y), pk2(av.z,av.z), pk2(av.w,av.w)};
#pragma unroll
        for (int op = 0; op < 2; op++)
#pragma unroll
            for (int p = 0; p < 4; p++) fma2(acc[op][p], wp[op], as[p]);
    }
}

// =====================================================================
// Fused kernel: 64-pos tile, 256 threads (8 warps), 2 CTAs/SM
// =====================================================================
__global__ void __launch_bounds__(256,2) fused_kernel(
    const float* __restrict__ xyz,
    const float* __restrict__ w1sc, const float* __restrict__ b1sc,
    const float* __restrict__ w1a,  const float* __restrict__ b1a,
    const float* __restrict__ w1b,  const float* __restrict__ b1b,
    const float* __restrict__ w1c,  const float* __restrict__ b1c,
    const float* __restrict__ w2sc, const float* __restrict__ b2sc,
    const float* __restrict__ w2a,  const float* __restrict__ b2a,
    const float* __restrict__ w2b,  const float* __restrict__ b2b,
    const float* __restrict__ w2c,  const float* __restrict__ b2c,
    float* __restrict__ outp)
{
    extern __shared__ float sm[];
    const int tid = threadIdx.x;
    const int pg = tid & 15, og = tid >> 4;   // og 0..15, pg 0..15
    const int base = blockIdx.x << 6;
    const int b  = base >> 17;
    const int n0 = (base & (NPTS*KNB - 1)) >> 4;
    const int nl = pg >> 2;                   // thread's 4 pos share n = n0+nl

    float4 R[4];

    // ---- Pro: LDG w1b ; feats + small weights + biases -> SC ----
    ldgA<64>(R, w1b, 0, tid);
    for (int l = tid; l < 640; l += 256) {
        int o = l/10, k = l - o*10;
        sm[SC + 680  + k*68 + o] = w1sc[l];
        sm[SC + 1360 + k*68 + o] = w1a[l];
    }
    if (tid < 64) {
        sm[SBIAS+tid] = b1sc[tid]; sm[SBIAS+64+tid] = b1a[tid];
        sm[SBIAS+128+tid] = b1b[tid]; sm[SBIAS+192+tid] = b1c[tid];
    }
    if (tid < 64) {
        int nn = n0 + (tid >> 4);
        const float* xb = xyz + b*3*NPTS;
        int j = g_idx[(b*NPTS + nn)*KNB + (tid & 15)];
        float cx = xb[nn], cy = xb[NPTS+nn], cz = xb[2*NPTS+nn];
        float nx = xb[j],  ny = xb[NPTS+j],  nz = xb[2*NPTS+j];
        float rx = nx-cx, ry = ny-cy, rz = nz-cz;
        float dd = sqrtf(fmaf(rx,rx, fmaf(ry,ry, rz*rz)) + 1e-12f);
        sm[SC+0*68+tid]=cx; sm[SC+1*68+tid]=cy; sm[SC+2*68+tid]=cz;
        sm[SC+3*68+tid]=nx; sm[SC+4*68+tid]=ny; sm[SC+5*68+tid]=nz;
        sm[SC+6*68+tid]=rx; sm[SC+7*68+tid]=ry; sm[SC+8*68+tid]=rz;
        sm[SC+9*68+tid]=dd;
    }
    __syncthreads();

    // ---- PK10: STS w1b->SW0 ; LDG w1c ; stage1 sc+a (K=10) ; h->SA sc->SB ----
    stsA(sm + SW0, R, tid);
    ldgA<64>(R, w1c, 0, tid);
    {
        u64 accS[2][4], accA[2][4];
#pragma unroll
        for (int op=0;op<2;op++)
#pragma unroll
            for (int p=0;p<4;p++) { accS[op][p]=0ull; accA[op][p]=0ull; }
#pragma unroll
        for (int k = 0; k < 10; k++) {
            ulonglong2 ws = *(const ulonglong2*)(sm + SC + 680  + k*68 + og*4);
            ulonglong2 wa = *(const ulonglong2*)(sm + SC + 1360 + k*68 + og*4);
            float4 av = *(const float4*)(sm + SC + k*68 + pg*4);
            u64 as[4] = {pk2(av.x,av.x), pk2(av.y,av.y), pk2(av.z,av.z), pk2(av.w,av.w)};
            u64 wsp[2] = {ws.x, ws.y}, wap[2] = {wa.x, wa.y};
#pragma unroll
            for (int op=0;op<2;op++)
#pragma unroll
                for (int p=0;p<4;p++) { fma2(accS[op][p], wsp[op], as[p]); fma2(accA[op][p], wap[op], as[p]); }
        }
#pragma unroll
        for (int op=0;op<2;op++) {
            int o0 = og*4 + 2*op;
            float ba0 = sm[SBIAS+64+o0], ba1 = sm[SBIAS+64+o0+1];
#pragma unroll
            for (int p=0;p<4;p++) {
                float2 va = up2(accA[op][p]);
                sm[SA + (o0  )*68 + pg*4 + p] = leaky(va.x + ba0);
                sm[SA + (o0+1)*68 + pg*4 + p] = leaky(va.y + ba1);
                float2 vs = up2(accS[op][p]);
                sm[SB + (o0  )*68 + pg*4 + p] = vs.x;
                sm[SB + (o0+1)*68 + pg*4 + p] = vs.y;
            }
        }
    }
    __syncthreads();

    u64 acc2[2][4];
#define ZERO2 {_Pragma("unroll") for (int op=0;op<2;op++) _Pragma("unroll") for (int p=0;p<4;p++) acc2[op][p]=0ull;}

    // ---- G1 [SW0=w1b]: stage1-b on SA(h) ; h2->SC ----
    stsA(sm + SW1, R, tid);          // w1c
    ldgA<128>(R, w2a, 0, tid);       // w2a main
    ZERO2
    gemmA64(sm + SW0, sm + SA, og, pg, acc2);
#pragma unroll
    for (int op=0;op<2;op++) {
        int o0 = og*4 + 2*op;
        float b0 = sm[SBIAS+128+o0], b1 = sm[SBIAS+128+o0+1];
#pragma unroll
        for (int p=0;p<4;p++) {
            float2 v = up2(acc2[op][p]);
            sm[SC + (o0  )*68 + pg*4 + p] = leaky(v.x + b0);
            sm[SC + (o0+1)*68 + pg*4 + p] = leaky(v.y + b1);
        }
    }
    __syncthreads();

    // ---- G2 [SW1=w1c]: stage1-c on SC(h2) ; out1->SB (+sc) ; x1 ----
    stsA(sm + SW0, R, tid);          // w2a main
    ldgA<128>(R, w2a, 64, tid);      // w2a corr cols
    ZERO2
    gemmA64(sm + SW1, sm + SC, og, pg, acc2);
#pragma unroll
    for (int op=0;op<2;op++) {
        int o0 = og*4 + 2*op;
        float bt0 = sm[SBIAS+192+o0] + sm[SBIAS+o0];
        float bt1 = sm[SBIAS+192+o0+1] + sm[SBIAS+o0+1];
        float v0m = -3.4e38f, v1m = -3.4e38f;
#pragma unroll
        for (int p=0;p<4;p++) {
            float2 v = up2(acc2[op][p]);
            float o0v = v.x + sm[SB + (o0  )*68 + pg*4 + p] + bt0;
            float o1v = v.y + sm[SB + (o0+1)*68 + pg*4 + p] + bt1;
            sm[SB + (o0  )*68 + pg*4 + p] = o0v;
            sm[SB + (o0+1)*68 + pg*4 + p] = o1v;
            v0m = fmaxf(v0m, o0v); v1m = fmaxf(v1m, o1v);
        }
        v0m = fmaxf(v0m, __shfl_xor_sync(0xffffffffu, v0m, 1));
        v0m = fmaxf(v0m, __shfl_xor_sync(0xffffffffu, v0m, 2));
        v1m = fmaxf(v1m, __shfl_xor_sync(0xffffffffu, v1m, 1));
        v1m = fmaxf(v1m, __shfl_xor_sync(0xffffffffu, v1m, 2));
        if ((pg & 3) == 0) {
            sm[SX1 + (o0  )*4 + nl] = v0m;
            sm[SX1 + (o0+1)*4 + nl] = v1m;
        }
    }
    __syncthreads();

    // ---- G3 [SW0=w2a main]: stage2-a main on SB(out1) ----
    stsA(sm + SW1, R, tid);          // w2a corr
    ldgB<64>(R, w2b, 0, tid);        // w2b chunk0
    u64 accA2[2][4];
#pragma unroll
    for (int op=0;op<2;op++)
#pragma unroll
        for (int p=0;p<4;p++) accA2[op][p]=0ull;
    gemmA64(sm + SW0, sm + SB, og, pg, accA2);
    __syncthreads();

    // ---- G4 [SW1=w2a corr]: x1-corr ; h -> SA ----
    stsB(sm + SW0, R, tid);          // w2b chunk0
    ldgB<64>(R, w2b, 32, tid);       // w2b chunk1
    {
        u64 crA[2] = {0,0};
#pragma unroll 4
        for (int c = 0; c < 64; c++) {
            ulonglong2 w01 = *(const ulonglong2*)(sm + SW1 + c*68 + og*4);
            float xv = sm[SX1 + c*4 + nl];
            u64 xs = pk2(xv, xv);
            fma2(crA[0], w01.x, xs); fma2(crA[1], w01.y, xs);
        }
#pragma unroll
        for (int op=0;op<2;op++) {
            int o0 = og*4 + 2*op;
            float2 c2 = up2(crA[op]);
            float b0 = __ldg(b2a + o0) + c2.x;
            float b1 = __ldg(b2a + o0 + 1) + c2.y;
#pragma unroll
            for (int p=0;p<4;p++) {
                float2 v = up2(accA2[op][p]);
                sm[SA + (o0  )*68 + pg*4 + p] = leaky(v.x + b0);
                sm[SA + (o0+1)*68 + pg*4 + p] = leaky(v.y + b1);
            }
        }
    }
    __syncthreads();

    // ---- G5/G6: stage2-b (two 32-k chunks) on SA(h) ----
    u64 accb[4][4];
#pragma unroll
    for (int op=0;op<4;op++)
#pragma unroll
        for (int p=0;p<4;p++) accb[op][p]=0ull;

    stsB(sm + SW1, R, tid);          // w2b chunk1
    ldgB<128>(R, w2c, 0, tid);       // w2c chunk0
    gemmB32(sm + SW0, sm + SA, og, pg, accb);
    __syncthreads();

    stsB(sm + SW0, R, tid);          // w2c chunk0
    ldgB<128>(R, w2c, 32, tid);      // w2c chunk1 (held across E1)
    gemmB32(sm + SW1, sm + SA + 32*68, og, pg, accb);
    __syncthreads();

    // ---- E1: h2 epilogue -> SA (ch<64) / SC (ch>=64) ----
    {
        float* dst = sm + ((og < 8) ? (SA + og*8*68) : (SC + (og-8)*8*68));
#pragma unroll
        for (int op=0;op<4;op++) {
            int o0 = og*8 + 2*op;
            float b0 = __ldg(b2b + o0), b1 = __ldg(b2b + o0+1);
#pragma unroll
            for (int p=0;p<4;p++) {
                float2 v = up2(accb[op][p]);
                dst[(2*op  )*68 + pg*4 + p] = leaky(v.x + b0);
                dst[(2*op+1)*68 + pg*4 + p] = leaky(v.y + b1);
            }
        }
    }
    __syncthreads();

    // ---- G7..G12: stage2 c (4 chunks) + sc main (2 chunks), one acc ----
    u64 acc[4][4];
#pragma unroll
    for (int op=0;op<4;op++)
#pragma unroll
        for (int p=0;p<4;p++) acc[op][p]=0ull;

    stsB(sm + SW1, R, tid);          // w2c chunk1
    ldgB<128>(R, w2c, 64, tid);
    gemmB32(sm + SW0, sm + SA, og, pg, acc);            // c k0-31 (h2 lo)
    __syncthreads();

    stsB(sm + SW0, R, tid);          // w2c chunk2
    ldgB<128>(R, w2c, 96, tid);
    gemmB32(sm + SW1, sm + SA + 32*68, og, pg, acc);    // c k32-63
    __syncthreads();

    stsB(sm + SW1, R, tid);          // w2c chunk3
    ldgB<128>(R, w2sc, 0, tid);
    gemmB32(sm + SW0, sm + SC, og, pg, acc);            // c k64-95 (h2 hi)
    __syncthreads();

    stsB(sm + SW0, R, tid);          // w2sc chunk0
    ldgB<128>(R, w2sc, 32, tid);
    gemmB32(sm + SW1, sm + SC + 32*68, og, pg, acc);    // c k96-127
    __syncthreads();

    stsB(sm + SW1, R, tid);          // w2sc chunk1
    ldgB<128>(R, w2sc, 64, tid);
    gemmB32(sm + SW0, sm + SB, og, pg, acc);            // sc k0-31 (out1)
    __syncthreads();

    stsB(sm + SW0, R, tid);          // w2sc corr chunk0 (cols 64-95)
    ldgB<128>(R, w2sc, 96, tid);
    gemmB32(sm + SW1, sm + SB + 32*68, og, pg, acc);    // sc k32-63
    __syncthreads();

    // ---- G13/G14: sc x1-corr (2 x 32 cols) ----
    u64 cr2[4] = {0,0,0,0};
    stsB(sm + SW1, R, tid);          // w2sc corr chunk1 (cols 96-127)
#pragma unroll 4
    for (int c = 0; c < 32; c++) {
        const float* wr = sm + SW0 + c*132 + og*8;
        ulonglong2 w01 = *(const ulonglong2*)wr;
        ulonglong2 w23 = *(const ulonglong2*)(wr+4);
        float xv = sm[SX1 + c*4 + nl];
        u64 xs = pk2(xv, xv);
        fma2(cr2[0], w01.x, xs); fma2(cr2[1], w01.y, xs);
        fma2(cr2[2], w23.x, xs); fma2(cr2[3], w23.y, xs);
    }
    __syncthreads();
#pragma unroll 4
    for (int c = 0; c < 32; c++) {
        const float* wr = sm + SW1 + c*132 + og*8;
        ulonglong2 w01 = *(const ulonglong2*)wr;
        ulonglong2 w23 = *(const ulonglong2*)(wr+4);
        float xv = sm[SX1 + (32+c)*4 + nl];
        u64 xs = pk2(xv, xv);
        fma2(cr2[0], w01.x, xs); fma2(cr2[1], w01.y, xs);
        fma2(cr2[2], w23.x, xs); fma2(cr2[3], w23.y, xs);
    }

    // ---- final epilogue: +biases +corr, max over 16 k, write ----
#pragma unroll
    for (int op=0;op<4;op++) {
        int o0 = og*8 + 2*op;
        float2 c2 = up2(cr2[op]);
        float bt0 = __ldg(b2sc + o0)     + __ldg(b2c + o0)     + c2.x;
        float bt1 = __ldg(b2sc + o0 + 1) + __ldg(b2c + o0 + 1) + c2.y;
        float m0 = -3.4e38f, m1 = -3.4e38f;
#pragma unroll
        for (int p=0;p<4;p++) {
            float2 v = up2(acc[op][p]);
            m0 = fmaxf(m0, v.x); m1 = fmaxf(m1, v.y);
        }
        m0 += bt0; m1 += bt1;
        m0 = fmaxf(m0, __shfl_xor_sync(0xffffffffu, m0, 1));
        m0 = fmaxf(m0, __shfl_xor_sync(0xffffffffu, m0, 2));
        m1 = fmaxf(m1, __shfl_xor_sync(0xffffffffu, m1, 1));
        m1 = fmaxf(m1, __shfl_xor_sync(0xffffffffu, m1, 2));
        if ((pg & 3) == 0) {
            outp[((long long)b*128 + o0    )*NPTS + n0 + nl] = m0;
            outp[((long long)b*128 + o0 + 1)*NPTS + n0 + nl] = m1;
        }
    }
}

// =====================================================================
extern "C" void kernel_launch(void* const* d_in, const int* in_sizes, int n_in,
                              void* d_out, int out_size)
{
    const float* xyz     = (const float*)d_in[0];
    const float* p1_sc_w = (const float*)d_in[1];
    const float* p1_sc_b = (const float*)d_in[2];
    const float* p1_a_w  = (const float*)d_in[3];
    const float* p1_a_b  = (const float*)d_in[4];
    const float* p1_b_w  = (const float*)d_in[5];
    const float* p1_b_b  = (const float*)d_in[6];
    const float* p1_c_w  = (const float*)d_in[7];
    const float* p1_c_b  = (const float*)d_in[8];
    const float* p2_sc_w = (const float*)d_in[9];
    const float* p2_sc_b = (const float*)d_in[10];
    const float* p2_a_w  = (const float*)d_in[11];
    const float* p2_a_b  = (const float*)d_in[12];
    const float* p2_b_w  = (const float*)d_in[13];
    const float* p2_b_b  = (const float*)d_in[14];
    const float* p2_c_w  = (const float*)d_in[15];
    const float* p2_c_b  = (const float*)d_in[16];
    float* outp = (float*)d_out;

    cudaFuncSetAttribute(fused_kernel, cudaFuncAttributeMaxDynamicSharedMemorySize,
                         SMEM_FLOATS*4);

    knn_part<<<BATCH*64*NPART, 128, 32768>>>(xyz);
    knn_merge<<<NQ/256, 256>>>();
    fused_kernel<<<NPOS/64, 256, SMEM_FLOATS*4>>>(
        xyz,
        p1_sc_w, p1_sc_b, p1_a_w, p1_a_b, p1_b_w, p1_b_b, p1_c_w, p1_c_b,
        p2_sc_w, p2_sc_b, p2_a_w, p2_a_b, p2_b_w, p2_b_b, p2_c_w, p2_c_b,
        outp);
}

// round 9
// speedup vs baseline: 1.1106x; 1.1106x over previous
#include <cuda_runtime.h>
#include <math.h>

#define BATCH 4
#define NPTS  8192
#define KNB   16
#define NPOS  (BATCH*NPTS*KNB)   // 524288
#define NQ    (BATCH*NPTS)       // 32768
#define CAP   48
#define NPART 4

__device__ int g_idx[NQ*KNB];
__device__ unsigned long long g_sbuf[(long long)NQ*NPART*CAP];
__device__ int g_scnt[NQ*NPART];

typedef unsigned long long u64;

__device__ __forceinline__ u64 pk2(float x, float y) {
    u64 r; asm("mov.b64 %0,{%1,%2};" : "=l"(r) : "f"(x), "f"(y)); return r;
}
__device__ __forceinline__ float2 up2(u64 v) {
    float2 r; asm("mov.b64 {%0,%1},%2;" : "=f"(r.x), "=f"(r.y) : "l"(v)); return r;
}
__device__ __forceinline__ void fma2(u64& d, u64 a, u64 b) {
    asm("fma.rn.f32x2 %0,%1,%2,%0;" : "+l"(d) : "l"(a), "l"(b));
}
__device__ __forceinline__ float leaky(float v) { return v >= 0.f ? v : 0.2f*v; }

// =====================================================================
// KNN helpers
// =====================================================================
__device__ __forceinline__ void bitonic32(float s[32]) {
#pragma unroll
    for (int k = 2; k <= 32; k <<= 1) {
#pragma unroll
        for (int j = k >> 1; j > 0; j >>= 1) {
#pragma unroll
            for (int ii = 0; ii < 32; ii++) {
                int l = ii ^ j;
                if (l > ii) {
                    float lo = fminf(s[ii], s[l]);
                    float hi = fmaxf(s[ii], s[l]);
                    bool up = ((ii & k) == 0);
                    s[ii] = up ? lo : hi;
                    s[l]  = up ? hi : lo;
                }
            }
        }
    }
}

// exact top-16 fallback over the tile (rare)
__device__ __forceinline__ void exact16(const float4* tile, float x2, float y2,
                                        float z2, int c0, u64 buf[16]) {
    float bd[16]; int bj[16];
#pragma unroll
    for (int t = 0; t < 16; t++) { bd[t] = 3.4e38f; bj[t] = 0; }
    float cm = 3.4e38f;
    for (int j = 0; j < 2048; j++) {
        float4 p = tile[j];
        float d = fmaf(x2, p.x, fmaf(y2, p.y, fmaf(z2, p.z, p.w)));
        if (d < cm) {
            int am = 0; float mv = bd[0];
#pragma unroll
            for (int u = 1; u < 16; u++) if (bd[u] > mv) { mv = bd[u]; am = u; }
#pragma unroll
            for (int u = 0; u < 16; u++) if (u == am) { bd[u] = d; bj[u] = c0 + j; }
            cm = bd[0];
#pragma unroll
            for (int u = 1; u < 16; u++) cm = fmaxf(cm, bd[u]);
        }
    }
#pragma unroll
    for (int t = 0; t < 16; t++) buf[t] = pk2(bd[t], __int_as_float(bj[t]));
}

// =====================================================================
// KNN part 1: branchless 2-pass top-16, TWO queries per thread.
// 512 blocks x 128 thr; block = 256 queries x one 2048-cand quarter.
// =====================================================================
__global__ __launch_bounds__(128) void knn_part(const float* __restrict__ xyz)
{
    extern __shared__ float4 tile[];   // 2048 * 16B = 32KB
    const int tid = threadIdx.x;
    const int quarter = blockIdx.x & 3;
    const int qb = (blockIdx.x >> 2) & 31;
    const int b  = blockIdx.x >> 7;
    const int i0 = qb*256 + tid;
    const int i1 = i0 + 128;
    const float* xb = xyz + b*3*NPTS;
    const int c0 = quarter*2048;

    for (int l = tid; l < 512; l += 128) {
        float4 vx = ((const float4*)(xb + c0))[l];
        float4 vy = ((const float4*)(xb + NPTS + c0))[l];
        float4 vz = ((const float4*)(xb + 2*NPTS + c0))[l];
        tile[4*l+0] = make_float4(vx.x, vy.x, vz.x, fmaf(vx.x,vx.x, fmaf(vy.x,vy.x, vz.x*vz.x)));
        tile[4*l+1] = make_float4(vx.y, vy.y, vz.y, fmaf(vx.y,vx.y, fmaf(vy.y,vy.y, vz.y*vz.y)));
        tile[4*l+2] = make_float4(vx.z, vy.z, vz.z, fmaf(vx.z,vx.z, fmaf(vy.z,vy.z, vz.z*vz.z)));
        tile[4*l+3] = make_float4(vx.w, vy.w, vz.w, fmaf(vx.w,vx.w, fmaf(vy.w,vy.w, vz.w*vz.w)));
    }
    __syncthreads();

    const float x20 = -2.0f*xb[i0], y20 = -2.0f*xb[NPTS+i0], z20 = -2.0f*xb[2*NPTS+i0];
    const float x21 = -2.0f*xb[i1], y21 = -2.0f*xb[NPTS+i1], z21 = -2.0f*xb[2*NPTS+i1];

    // pass A: 32 residue-slot minima per query, branchless, shared LDS
    float s0[32], s1[32];
#pragma unroll
    for (int t = 0; t < 32; t++) { s0[t] = 3.4e38f; s1[t] = 3.4e38f; }
    for (int j0 = 0; j0 < 2048; j0 += 32) {
#pragma unroll
        for (int u = 0; u < 32; u++) {
            float4 p = tile[j0+u];
            float d0 = fmaf(x20, p.x, fmaf(y20, p.y, fmaf(z20, p.z, p.w)));
            float d1 = fmaf(x21, p.x, fmaf(y21, p.y, fmaf(z21, p.z, p.w)));
            s0[u] = fminf(s0[u], d0);
            s1[u] = fminf(s1[u], d1);
        }
    }

    bitonic32(s0);
    bitonic32(s1);
    const float T0 = s0[15], T1 = s1[15];

    // pass B: collect survivors for both queries (>=16 each guaranteed)
    u64 buf0[CAP], buf1[CAP];
    int cnt0 = 0, cnt1 = 0, ovf0 = 0, ovf1 = 0;
    for (int j = 0; j < 2048; j++) {
        float4 p = tile[j];
        float d0 = fmaf(x20, p.x, fmaf(y20, p.y, fmaf(z20, p.z, p.w)));
        float d1 = fmaf(x21, p.x, fmaf(y21, p.y, fmaf(z21, p.z, p.w)));
        if (d0 <= T0) {
            if (cnt0 < CAP) { buf0[cnt0] = pk2(d0, __int_as_float(c0+j)); cnt0++; }
            else ovf0 = 1;
        }
        if (d1 <= T1) {
            if (cnt1 < CAP) { buf1[cnt1] = pk2(d1, __int_as_float(c0+j)); cnt1++; }
            else ovf1 = 1;
        }
    }

    if (ovf0) { exact16(tile, x20, y20, z20, c0, buf0); cnt0 = 16; }
    if (ovf1) { exact16(tile, x21, y21, z21, c0, buf1); cnt1 = 16; }

    {
        const int qg = b*NPTS + i0;
        g_scnt[qg*NPART + quarter] = cnt0;
        u64* dst = g_sbuf + (long long)(qg*NPART + quarter)*CAP;
        for (int t = 0; t < cnt0; t++) dst[t] = buf0[t];
    }
    {
        const int qg = b*NPTS + i1;
        g_scnt[qg*NPART + quarter] = cnt1;
        u64* dst = g_sbuf + (long long)(qg*NPART + quarter)*CAP;
        for (int t = 0; t < cnt1; t++) dst[t] = buf1[t];
    }
}

// =====================================================================
// KNN part 2: exact top-16 over pooled survivors (4 parts)
// =====================================================================
__global__ __launch_bounds__(256) void knn_merge()
{
    const int q = blockIdx.x*256 + threadIdx.x;
    float bd[16]; int bj[16];
#pragma unroll
    for (int t = 0; t < 16; t++) { bd[t] = 3.4e38f; bj[t] = 0; }
    float cm = 3.4e38f;
#pragma unroll
    for (int h = 0; h < NPART; h++) {
        const int c = g_scnt[q*NPART + h];
        const u64* src = g_sbuf + (long long)(q*NPART + h)*CAP;
        for (int e = 0; e < c; e++) {
            float2 v = up2(src[e]);
            float d = v.x;
            if (d < cm) {
                int am = 0; float mv = bd[0];
#pragma unroll
                for (int u = 1; u < 16; u++) if (bd[u] > mv) { mv = bd[u]; am = u; }
#pragma unroll
                for (int u = 0; u < 16; u++) if (u == am) { bd[u] = d; bj[u] = __float_as_int(v.y); }
                cm = bd[0];
#pragma unroll
                for (int u = 1; u < 16; u++) cm = fmaxf(cm, bd[u]);
            }
        }
    }
#pragma unroll
    for (int t = 0; t < 16; t++) g_idx[q*16 + t] = bj[t];
}

// =====================================================================
// smem layout (floats) — fused kernel (R6 verbatim: 128 thr, 3 CTAs/SM)
// =====================================================================
#define SA    0        // 4352
#define SB    4352     // 4352
#define SC    8704     // 4352
#define SW0   13056    // 2176 ping
#define SW1   15232    // 2176 pong
#define SX1   17408    // 256
#define SBIAS 17664    // 256
#define SMEM_FLOATS 17920   // 71680 B -> 3 CTAs/SM

template<int KFULL>
__device__ __forceinline__ void ldgA(float4 r[4], const float* __restrict__ src,
                                     int koff, int tid)
{
#pragma unroll
    for (int it = 0; it < 4; it++) {
        int l = it*128 + tid;
        int o = l & 63, k4 = l >> 6;
        r[it] = *(const float4*)(src + o*KFULL + koff + 4*k4);
    }
}
__device__ __forceinline__ void stsA(float* __restrict__ dst, const float4 r[4], int tid)
{
#pragma unroll
    for (int it = 0; it < 4; it++) {
        int l = it*128 + tid;
        int o = l & 63, k = (l >> 6)*4;
        dst[(k  )*68+o] = r[it].x; dst[(k+1)*68+o] = r[it].y;
        dst[(k+2)*68+o] = r[it].z; dst[(k+3)*68+o] = r[it].w;
    }
}
template<int KFULL>
__device__ __forceinline__ void ldgB(float4 r[4], const float* __restrict__ src,
                                     int koff, int tid)
{
#pragma unroll
    for (int it = 0; it < 4; it++) {
        int l = it*128 + tid;
        int o = l & 127, k4 = l >> 7;
        r[it] = *(const float4*)(src + o*KFULL + koff + 4*k4);
    }
}
__device__ __forceinline__ void stsB(float* __restrict__ dst, const float4 r[4], int tid)
{
#pragma unroll
    for (int it = 0; it < 4; it++) {
        int l = it*128 + tid;
        int o = l & 127, k = (l >> 7)*4;
        dst[(k  )*132+o] = r[it].x; dst[(k+1)*132+o] = r[it].y;
        dst[(k+2)*132+o] = r[it].z; dst[(k+3)*132+o] = r[it].w;
    }
}

// 16 out (8 pairs) x 4 pos. w: [k][o] stride 132.
template<int KS>
__device__ __forceinline__ void gemm16(const float* __restrict__ w,
                                       const float* __restrict__ a,
                                       int og, int pg, u64 acc[8][4])
{
#pragma unroll 4
    for (int k = 0; k < KS; k++) {
        const float* wr = w + k*132 + og*16;
        ulonglong2 w01 = *(const ulonglong2*)wr;
        ulonglong2 w23 = *(const ulonglong2*)(wr+4);
        ulonglong2 w45 = *(const ulonglong2*)(wr+8);
        ulonglong2 w67 = *(const ulonglong2*)(wr+12);
        u64 wp[8] = {w01.x,w01.y,w23.x,w23.y,w45.x,w45.y,w67.x,w67.y};
        float4 av = *(const float4*)(a + k*68 + pg*4);
        u64 as[4] = {pk2(av.x,av.x), pk2(av.y,av.y), pk2(av.z,av.z), pk2(av.w,av.w)};
#pragma unroll
        for (int op = 0; op < 8; op++)
#pragma unroll
            for (int p = 0; p < 4; p++) fma2(acc[op][p], wp[op], as[p]);
    }
}

// 8 out (4 pairs) x 4 pos. w: [k][o] stride 68.
template<int KS>
__device__ __forceinline__ void gemm8(const float* __restrict__ w,
                                      const float* __restrict__ a,
                                      int og, int pg, u64 acc[4][4])
{
#pragma unroll 4
    for (int k = 0; k < KS; k++) {
        const float* wr = w + k*68 + og*8;
        ulonglong2 w01 = *(const ulonglong2*)wr;
        ulonglong2 w23 = *(const ulonglong2*)(wr+4);
        u64 wp[4] = {w01.x,w01.y,w23.x,w23.y};
        float4 av = *(const float4*)(a + k*68 + pg*4);
        u64 as[4] = {pk2(av.x,av.x), pk2(av.y,av.y), pk2(av.z,av.z), pk2(av.w,av.w)};
#pragma unroll
        for (int op = 0; op < 4; op++)
#pragma unroll
            for (int p = 0; p < 4; p++) fma2(acc[op][p], wp[op], as[p]);
    }
}

// =====================================================================
// Fused kernel (R6 verbatim): 64-pos tile, 128 threads, 3 CTAs/SM
// =====================================================================
__global__ void __launch_bounds__(128,3) fused_kernel(
    const float* __restrict__ xyz,
    const float* __restrict__ w1sc, const float* __restrict__ b1sc,
    const float* __restrict__ w1a,  const float* __restrict__ b1a,
    const float* __restrict__ w1b,  const float* __restrict__ b1b,
    const float* __restrict__ w1c,  const float* __restrict__ b1c,
    const float* __restrict__ w2sc, const float* __restrict__ b2sc,
    const float* __restrict__ w2a,  const float* __restrict__ b2a,
    const float* __restrict__ w2b,  const float* __restrict__ b2b,
    const float* __restrict__ w2c,  const float* __restrict__ b2c,
    float* __restrict__ outp)
{
    extern __shared__ float sm[];
    const int tid = threadIdx.x;
    const int pg = tid & 15, og = tid >> 4;
    const int base = blockIdx.x << 6;
    const int b  = base >> 17;
    const int n0 = (base & (NPTS*KNB - 1)) >> 4;
    const int nl = pg >> 2;

    float4 R[4];

    ldgA<64>(R, w1b, 0, tid);
    for (int l = tid; l < 640; l += 128) {
        int o = l/10, k = l - o*10;
        sm[SC + 680  + k*68 + o] = w1sc[l];
        sm[SC + 1360 + k*68 + o] = w1a[l];
    }
    if (tid < 64) {
        sm[SBIAS+tid] = b1sc[tid]; sm[SBIAS+64+tid] = b1a[tid];
        sm[SBIAS+128+tid] = b1b[tid]; sm[SBIAS+192+tid] = b1c[tid];
    }
    if (tid < 64) {
        int nn = n0 + (tid >> 4);
        const float* xb = xyz + b*3*NPTS;
        int j = g_idx[(b*NPTS + nn)*KNB + (tid & 15)];
        float cx = xb[nn], cy = xb[NPTS+nn], cz = xb[2*NPTS+nn];
        float nx = xb[j],  ny = xb[NPTS+j],  nz = xb[2*NPTS+j];
        float rx = nx-cx, ry = ny-cy, rz = nz-cz;
        float dd = sqrtf(fmaf(rx,rx, fmaf(ry,ry, rz*rz)) + 1e-12f);
        sm[SC+0*68+tid]=cx; sm[SC+1*68+tid]=cy; sm[SC+2*68+tid]=cz;
        sm[SC+3*68+tid]=nx; sm[SC+4*68+tid]=ny; sm[SC+5*68+tid]=nz;
        sm[SC+6*68+tid]=rx; sm[SC+7*68+tid]=ry; sm[SC+8*68+tid]=rz;
        sm[SC+9*68+tid]=dd;
    }
    __syncthreads();

    stsA(sm + SW0, R, tid);
    ldgA<64>(R, w1c, 0, tid);
    {
        u64 accS[4][4], accA[4][4];
#pragma unroll
        for (int op=0;op<4;op++)
#pragma unroll
            for (int p=0;p<4;p++) { accS[op][p]=0ull; accA[op][p]=0ull; }
#pragma unroll
        for (int k = 0; k < 10; k++) {
            const float* wsr = sm + SC + 680  + k*68 + og*8;
            const float* war = sm + SC + 1360 + k*68 + og*8;
            ulonglong2 ws01 = *(const ulonglong2*)wsr;
            ulonglong2 ws23 = *(const ulonglong2*)(wsr+4);
            ulonglong2 wa01 = *(const ulonglong2*)war;
            ulonglong2 wa23 = *(const ulonglong2*)(war+4);
            u64 wsp[4] = {ws01.x,ws01.y,ws23.x,ws23.y};
            u64 wap[4] = {wa01.x,wa01.y,wa23.x,wa23.y};
            float4 av = *(const float4*)(sm + SC + k*68 + pg*4);
            u64 as[4] = {pk2(av.x,av.x), pk2(av.y,av.y), pk2(av.z,av.z), pk2(av.w,av.w)};
#pragma unroll
            for (int op=0;op<4;op++)
#pragma unroll
                for (int p=0;p<4;p++) { fma2(accS[op][p], wsp[op], as[p]); fma2(accA[op][p], wap[op], as[p]); }
        }
#pragma unroll
        for (int op=0;op<4;op++) {
            int o0 = og*8 + 2*op;
            float ba0 = sm[SBIAS+64+o0], ba1 = sm[SBIAS+64+o0+1];
#pragma unroll
            for (int p=0;p<4;p++) {
                float2 va = up2(accA[op][p]);
                sm[SA + (o0  )*68 + pg*4 + p] = leaky(va.x + ba0);
                sm[SA + (o0+1)*68 + pg*4 + p] = leaky(va.y + ba1);
                float2 vs = up2(accS[op][p]);
                sm[SB + (o0  )*68 + pg*4 + p] = vs.x;
                sm[SB + (o0+1)*68 + pg*4 + p] = vs.y;
            }
        }
    }
    __syncthreads();

    u64 acc4[4][4];
#define ZERO4 {_Pragma("unroll") for (int op=0;op<4;op++) _Pragma("unroll") for (int p=0;p<4;p++) acc4[op][p]=0ull;}

    ldgA<64>(R, w1b, 32, tid);
    ZERO4
    gemm8<32>(sm + SW0, sm + SA, og, pg, acc4);
    stsA(sm + SW1, R, tid);
    __syncthreads();

    ldgA<64>(R, w1c, 0, tid);
    gemm8<32>(sm + SW1, sm + SA + 32*68, og, pg, acc4);
#pragma unroll
    for (int op=0;op<4;op++) {
        int o0 = og*8 + 2*op;
        float b0 = sm[SBIAS+128+o0], b1 = sm[SBIAS+128+o0+1];
#pragma unroll
        for (int p=0;p<4;p++) {
            float2 v = up2(acc4[op][p]);
            sm[SC + (o0  )*68 + pg*4 + p] = leaky(v.x + b0);
            sm[SC + (o0+1)*68 + pg*4 + p] = leaky(v.y + b1);
        }
    }
    stsA(sm + SW0, R, tid);
    __syncthreads();

    ldgA<64>(R, w1c, 32, tid);
    ZERO4
    gemm8<32>(sm + SW0, sm + SC, og, pg, acc4);
    stsA(sm + SW1, R, tid);
    __syncthreads();

    ldgA<128>(R, w2a, 0, tid);
    gemm8<32>(sm + SW1, sm + SC + 32*68, og, pg, acc4);
#pragma unroll
    for (int op=0;op<4;op++) {
        int o0 = og*8 + 2*op;
        float bt0 = sm[SBIAS+192+o0] + sm[SBIAS+o0];
        float bt1 = sm[SBIAS+192+o0+1] + sm[SBIAS+o0+1];
        float v0m = -3.4e38f, v1m = -3.4e38f;
#pragma unroll
        for (int p=0;p<4;p++) {
            float2 v = up2(acc4[op][p]);
            float o0v = v.x + sm[SB + (o0  )*68 + pg*4 + p] + bt0;
            float o1v = v.y + sm[SB + (o0+1)*68 + pg*4 + p] + bt1;
            sm[SB + (o0  )*68 + pg*4 + p] = o0v;
            sm[SB + (o0+1)*68 + pg*4 + p] = o1v;
            v0m = fmaxf(v0m, o0v); v1m = fmaxf(v1m, o1v);
        }
        v0m = fmaxf(v0m, __shfl_xor_sync(0xffffffffu, v0m, 1));
        v0m = fmaxf(v0m, __shfl_xor_sync(0xffffffffu, v0m, 2));
        v1m = fmaxf(v1m, __shfl_xor_sync(0xffffffffu, v1m, 1));
        v1m = fmaxf(v1m, __shfl_xor_sync(0xffffffffu, v1m, 2));
        if ((pg & 3) == 0) {
            sm[SX1 + (o0  )*4 + nl] = v0m;
            sm[SX1 + (o0+1)*4 + nl] = v1m;
        }
    }
    stsA(sm + SW0, R, tid);
    __syncthreads();

    ldgA<128>(R, w2a, 32, tid);
    ZERO4
    gemm8<32>(sm + SW0, sm + SB, og, pg, acc4);
    stsA(sm + SW1, R, tid);
    __syncthreads();

    ldgA<128>(R, w2a, 64, tid);
    gemm8<32>(sm + SW1, sm + SB + 32*68, og, pg, acc4);
    stsA(sm + SW0, R, tid);
    __syncthreads();

    u64 crA[4] = {0,0,0,0};
    ldgA<128>(R, w2a, 96, tid);
#pragma unroll 4
    for (int c = 0; c < 32; c++) {
        const float* wr = sm + SW0 + c*68 + og*8;
        ulonglong2 w01 = *(const ulonglong2*)wr;
        ulonglong2 w23 = *(const ulonglong2*)(wr+4);
        float xv = sm[SX1 + c*4 + nl];
        u64 xs = pk2(xv, xv);
        fma2(crA[0], w01.x, xs); fma2(crA[1], w01.y, xs);
        fma2(crA[2], w23.x, xs); fma2(crA[3], w23.y, xs);
    }
    stsA(sm + SW1, R, tid);
    __syncthreads();

    ldgB<64>(R, w2b, 0, tid);
#pragma unroll 4
    for (int c = 0; c < 32; c++) {
        const float* wr = sm + SW1 + c*68 + og*8;
        ulonglong2 w01 = *(const ulonglong2*)wr;
        ulonglong2 w23 = *(const ulonglong2*)(wr+4);
        float xv = sm[SX1 + (32+c)*4 + nl];
        u64 xs = pk2(xv, xv);
        fma2(crA[0], w01.x, xs); fma2(crA[1], w01.y, xs);
        fma2(crA[2], w23.x, xs); fma2(crA[3], w23.y, xs);
    }
#pragma unroll
    for (int op=0;op<4;op++) {
        int o0 = og*8 + 2*op;
        float2 c2 = up2(crA[op]);
        float b0 = __ldg(b2a + o0) + c2.x;
        float b1 = __ldg(b2a + o0 + 1) + c2.y;
#pragma unroll
        for (int p=0;p<4;p++) {
            float2 v = up2(acc4[op][p]);
            sm[SA + (o0  )*68 + pg*4 + p] = leaky(v.x + b0);
            sm[SA + (o0+1)*68 + pg*4 + p] = leaky(v.y + b1);
        }
    }
    stsB(sm + SW0, R, tid);
    __syncthreads();

    u64 acc[8][4];
#pragma unroll
    for (int op=0;op<8;op++)
#pragma unroll
        for (int p=0;p<4;p++) acc[op][p]=0ull;

    ldgB<64>(R, w2b, 16, tid);
    gemm16<16>(sm + SW0, sm + SA, og, pg, acc);
    stsB(sm + SW1, R, tid);
    __syncthreads();

    ldgB<64>(R, w2b, 32, tid);
    gemm16<16>(sm + SW1, sm + SA + 16*68, og, pg, acc);
    stsB(sm + SW0, R, tid);
    __syncthreads();

    ldgB<64>(R, w2b, 48, tid);
    gemm16<16>(sm + SW0, sm + SA + 32*68, og, pg, acc);
    stsB(sm + SW1, R, tid);
    __syncthreads();

    ldgB<128>(R, w2c, 0, tid);
    gemm16<16>(sm + SW1, sm + SA + 48*68, og, pg, acc);
    __syncthreads();
#pragma unroll
    for (int op=0;op<8;op++) {
        int o0 = og*16 + 2*op;
        float b0 = __ldg(b2b + o0), b1 = __ldg(b2b + o0+1);
        float* d0 = sm + ((o0 < 64) ? (SA + o0*68) : (SC + (o0-64)*68));
        float* d1 = sm + ((o0+1 < 64) ? (SA + (o0+1)*68) : (SC + (o0+1-64)*68));
#pragma unroll
        for (int p=0;p<4;p++) {
            float2 v = up2(acc[op][p]);
            d0[pg*4 + p] = leaky(v.x + b0);
            d1[pg*4 + p] = leaky(v.y + b1);
        }
    }
    stsB(sm + SW0, R, tid);
    __syncthreads();

#pragma unroll
    for (int op=0;op<8;op++)
#pragma unroll
        for (int p=0;p<4;p++) acc[op][p]=0ull;

    ldgB<128>(R, w2c, 16, tid);
    gemm16<16>(sm + SW0, sm + SA, og, pg, acc);
    stsB(sm + SW1, R, tid); __syncthreads();

    ldgB<128>(R, w2c, 32, tid);
    gemm16<16>(sm + SW1, sm + SA + 16*68, og, pg, acc);
    stsB(sm + SW0, R, tid); __syncthreads();

    ldgB<128>(R, w2c, 48, tid);
    gemm16<16>(sm + SW0, sm + SA + 32*68, og, pg, acc);
    stsB(sm + SW1, R, tid); __syncthreads();

    ldgB<128>(R, w2c, 64, tid);
    gemm16<16>(sm + SW1, sm + SA + 48*68, og, pg, acc);
    stsB(sm + SW0, R, tid); __syncthreads();

    ldgB<128>(R, w2c, 80, tid);
    gemm16<16>(sm + SW0, sm + SC, og, pg, acc);
    stsB(sm + SW1, R, tid); __syncthreads();

    ldgB<128>(R, w2c, 96, tid);
    gemm16<16>(sm + SW1, sm + SC + 16*68, og, pg, acc);
    stsB(sm + SW0, R, tid); __syncthreads();

    ldgB<128>(R, w2c, 112, tid);
    gemm16<16>(sm + SW0, sm + SC + 32*68, og, pg, acc);
    stsB(sm + SW1, R, tid); __syncthreads();

    ldgB<128>(R, w2sc, 0, tid);
    gemm16<16>(sm + SW1, sm + SC + 48*68, og, pg, acc);
    stsB(sm + SW0, R, tid); __syncthreads();

    ldgB<128>(R, w2sc, 16, tid);
    gemm16<16>(sm + SW0, sm + SB, og, pg, acc);
    stsB(sm + SW1, R, tid); __syncthreads();

    ldgB<128>(R, w2sc, 32, tid);
    gemm16<16>(sm + SW1, sm + SB + 16*68, og, pg, acc);
    stsB(sm + SW0, R, tid); __syncthreads();

    ldgB<128>(R, w2sc, 48, tid);
    gemm16<16>(sm + SW0, sm + SB + 32*68, og, pg, acc);
    stsB(sm + SW1, R, tid); __syncthreads();

    ldgB<128>(R, w2sc, 64, tid);
    gemm16<16>(sm + SW1, sm + SB + 48*68, og, pg, acc);
    stsB(sm + SW0, R, tid); __syncthreads();

    u64 cr2[8] = {0,0,0,0,0,0,0,0};
#define CORR16(BUF, C0) \
    _Pragma("unroll 4") \
    for (int cc = 0; cc < 16; cc++) { \
        const float* wr = sm + (BUF) + cc*132 + og*16; \
        ulonglong2 w01 = *(const ulonglong2*)wr; \
        ulonglong2 w23 = *(const ulonglong2*)(wr+4); \
        ulonglong2 w45 = *(const ulonglong2*)(wr+8); \
        ulonglong2 w67 = *(const ulonglong2*)(wr+12); \
        float xv = sm[SX1 + ((C0)+cc)*4 + nl]; \
        u64 xs = pk2(xv, xv); \
        fma2(cr2[0], w01.x, xs); fma2(cr2[1], w01.y, xs); \
        fma2(cr2[2], w23.x, xs); fma2(cr2[3], w23.y, xs); \
        fma2(cr2[4], w45.x, xs); fma2(cr2[5], w45.y, xs); \
        fma2(cr2[6], w67.x, xs); fma2(cr2[7], w67.y, xs); \
    }

    ldgB<128>(R, w2sc, 80, tid);
    CORR16(SW0, 0)
    stsB(sm + SW1, R, tid); __syncthreads();

    ldgB<128>(R, w2sc, 96, tid);
    CORR16(SW1, 16)
    stsB(sm + SW0, R, tid); __syncthreads();

    ldgB<128>(R, w2sc, 112, tid);
    CORR16(SW0, 32)
    stsB(sm + SW1, R, tid); __syncthreads();

    CORR16(SW1, 48)

#pragma unroll
    for (int op=0;op<8;op++) {
        int o0 = og*16 + 2*op;
        float2 c2 = up2(cr2[op]);
        float bt0 = __ldg(b2sc + o0)     + __ldg(b2c + o0)     + c2.x;
        float bt1 = __ldg(b2sc + o0 + 1) + __ldg(b2c + o0 + 1) + c2.y;
        float m0 = -3.4e38f, m1 = -3.4e38f;
#pragma unroll
        for (int p=0;p<4;p++) {
            float2 v = up2(acc[op][p]);
            m0 = fmaxf(m0, v.x); m1 = fmaxf(m1, v.y);
        }
        m0 += bt0; m1 += bt1;
        m0 = fmaxf(m0, __shfl_xor_sync(0xffffffffu, m0, 1));
        m0 = fmaxf(m0, __shfl_xor_sync(0xffffffffu, m0, 2));
        m1 = fmaxf(m1, __shfl_xor_sync(0xffffffffu, m1, 1));
        m1 = fmaxf(m1, __shfl_xor_sync(0xffffffffu, m1, 2));
        if ((pg & 3) == 0) {
            outp[((long long)b*128 + o0    )*NPTS + n0 + nl] = m0;
            outp[((long long)b*128 + o0 + 1)*NPTS + n0 + nl] = m1;
        }
    }
}

// =====================================================================
extern "C" void kernel_launch(void* const* d_in, const int* in_sizes, int n_in,
                              void* d_out, int out_size)
{
    const float* xyz     = (const float*)d_in[0];
    const float* p1_sc_w = (const float*)d_in[1];
    const float* p1_sc_b = (const float*)d_in[2];
    const float* p1_a_w  = (const float*)d_in[3];
    const float* p1_a_b  = (const float*)d_in[4];
    const float* p1_b_w  = (const float*)d_in[5];
    const float* p1_b_b  = (const float*)d_in[6];
    const float* p1_c_w  = (const float*)d_in[7];
    const float* p1_c_b  = (const float*)d_in[8];
    const float* p2_sc_w = (const float*)d_in[9];
    const float* p2_sc_b = (const float*)d_in[10];
    const float* p2_a_w  = (const float*)d_in[11];
    const float* p2_a_b  = (const float*)d_in[12];
    const float* p2_b_w  = (const float*)d_in[13];
    const float* p2_b_b  = (const float*)d_in[14];
    const float* p2_c_w  = (const float*)d_in[15];
    const float* p2_c_b  = (const float*)d_in[16];
    float* outp = (float*)d_out;

    cudaFuncSetAttribute(fused_kernel, cudaFuncAttributeMaxDynamicSharedMemorySize,
                         SMEM_FLOATS*4);

    knn_part<<<512, 128, 32768>>>(xyz);
    knn_merge<<<NQ/256, 256>>>();
    fused_kernel<<<NPOS/64, 128, SMEM_FLOATS*4>>>(
        xyz,
        p1_sc_w, p1_sc_b, p1_a_w, p1_a_b, p1_b_w, p1_b_b, p1_c_w, p1_c_b,
        p2_sc_w, p2_sc_b, p2_a_w, p2_a_b, p2_b_w, p2_b_b, p2_c_w, p2_c_b,
        outp);
}

// round 10
// speedup vs baseline: 1.1510x; 1.0364x over previous
#include <cuda_runtime.h>
#include <math.h>

#define BATCH 4
#define NPTS  8192
#define KNB   16
#define NPOS  (BATCH*NPTS*KNB)   // 524288
#define NQ    (BATCH*NPTS)       // 32768
#define CAP   48
#define NPART 4

__device__ int g_idx[NQ*KNB];
__device__ unsigned long long g_sbuf[(long long)NQ*NPART*CAP];
__device__ int g_scnt[NQ*NPART];

typedef unsigned long long u64;

__device__ __forceinline__ u64 pk2(float x, float y) {
    u64 r; asm("mov.b64 %0,{%1,%2};" : "=l"(r) : "f"(x), "f"(y)); return r;
}
__device__ __forceinline__ float2 up2(u64 v) {
    float2 r; asm("mov.b64 {%0,%1},%2;" : "=f"(r.x), "=f"(r.y) : "l"(v)); return r;
}
__device__ __forceinline__ void fma2(u64& d, u64 a, u64 b) {
    asm("fma.rn.f32x2 %0,%1,%2,%0;" : "+l"(d) : "l"(a), "l"(b));
}
__device__ __forceinline__ float leaky(float v) { return v >= 0.f ? v : 0.2f*v; }

// =====================================================================
// KNN (unchanged from R9)
// =====================================================================
__device__ __forceinline__ void bitonic32(float s[32]) {
#pragma unroll
    for (int k = 2; k <= 32; k <<= 1) {
#pragma unroll
        for (int j = k >> 1; j > 0; j >>= 1) {
#pragma unroll
            for (int ii = 0; ii < 32; ii++) {
                int l = ii ^ j;
                if (l > ii) {
                    float lo = fminf(s[ii], s[l]);
                    float hi = fmaxf(s[ii], s[l]);
                    bool up = ((ii & k) == 0);
                    s[ii] = up ? lo : hi;
                    s[l]  = up ? hi : lo;
                }
            }
        }
    }
}

__device__ __forceinline__ void exact16(const float4* tile, float x2, float y2,
                                        float z2, int c0, u64 buf[16]) {
    float bd[16]; int bj[16];
#pragma unroll
    for (int t = 0; t < 16; t++) { bd[t] = 3.4e38f; bj[t] = 0; }
    float cm = 3.4e38f;
    for (int j = 0; j < 2048; j++) {
        float4 p = tile[j];
        float d = fmaf(x2, p.x, fmaf(y2, p.y, fmaf(z2, p.z, p.w)));
        if (d < cm) {
            int am = 0; float mv = bd[0];
#pragma unroll
            for (int u = 1; u < 16; u++) if (bd[u] > mv) { mv = bd[u]; am = u; }
#pragma unroll
            for (int u = 0; u < 16; u++) if (u == am) { bd[u] = d; bj[u] = c0 + j; }
            cm = bd[0];
#pragma unroll
            for (int u = 1; u < 16; u++) cm = fmaxf(cm, bd[u]);
        }
    }
#pragma unroll
    for (int t = 0; t < 16; t++) buf[t] = pk2(bd[t], __int_as_float(bj[t]));
}

__global__ __launch_bounds__(128) void knn_part(const float* __restrict__ xyz)
{
    extern __shared__ float4 tile[];
    const int tid = threadIdx.x;
    const int quarter = blockIdx.x & 3;
    const int qb = (blockIdx.x >> 2) & 31;
    const int b  = blockIdx.x >> 7;
    const int i0 = qb*256 + tid;
    const int i1 = i0 + 128;
    const float* xb = xyz + b*3*NPTS;
    const int c0 = quarter*2048;

    for (int l = tid; l < 512; l += 128) {
        float4 vx = ((const float4*)(xb + c0))[l];
        float4 vy = ((const float4*)(xb + NPTS + c0))[l];
        float4 vz = ((const float4*)(xb + 2*NPTS + c0))[l];
        tile[4*l+0] = make_float4(vx.x, vy.x, vz.x, fmaf(vx.x,vx.x, fmaf(vy.x,vy.x, vz.x*vz.x)));
        tile[4*l+1] = make_float4(vx.y, vy.y, vz.y, fmaf(vx.y,vx.y, fmaf(vy.y,vy.y, vz.y*vz.y)));
        tile[4*l+2] = make_float4(vx.z, vy.z, vz.z, fmaf(vx.z,vx.z, fmaf(vy.z,vy.z, vz.z*vz.z)));
        tile[4*l+3] = make_float4(vx.w, vy.w, vz.w, fmaf(vx.w,vx.w, fmaf(vy.w,vy.w, vz.w*vz.w)));
    }
    __syncthreads();

    const float x20 = -2.0f*xb[i0], y20 = -2.0f*xb[NPTS+i0], z20 = -2.0f*xb[2*NPTS+i0];
    const float x21 = -2.0f*xb[i1], y21 = -2.0f*xb[NPTS+i1], z21 = -2.0f*xb[2*NPTS+i1];

    float s0[32], s1[32];
#pragma unroll
    for (int t = 0; t < 32; t++) { s0[t] = 3.4e38f; s1[t] = 3.4e38f; }
    for (int j0 = 0; j0 < 2048; j0 += 32) {
#pragma unroll
        for (int u = 0; u < 32; u++) {
            float4 p = tile[j0+u];
            float d0 = fmaf(x20, p.x, fmaf(y20, p.y, fmaf(z20, p.z, p.w)));
            float d1 = fmaf(x21, p.x, fmaf(y21, p.y, fmaf(z21, p.z, p.w)));
            s0[u] = fminf(s0[u], d0);
            s1[u] = fminf(s1[u], d1);
        }
    }

    bitonic32(s0);
    bitonic32(s1);
    const float T0 = s0[15], T1 = s1[15];

    u64 buf0[CAP], buf1[CAP];
    int cnt0 = 0, cnt1 = 0, ovf0 = 0, ovf1 = 0;
    for (int j = 0; j < 2048; j++) {
        float4 p = tile[j];
        float d0 = fmaf(x20, p.x, fmaf(y20, p.y, fmaf(z20, p.z, p.w)));
        float d1 = fmaf(x21, p.x, fmaf(y21, p.y, fmaf(z21, p.z, p.w)));
        if (d0 <= T0) {
            if (cnt0 < CAP) { buf0[cnt0] = pk2(d0, __int_as_float(c0+j)); cnt0++; }
            else ovf0 = 1;
        }
        if (d1 <= T1) {
            if (cnt1 < CAP) { buf1[cnt1] = pk2(d1, __int_as_float(c0+j)); cnt1++; }
            else ovf1 = 1;
        }
    }

    if (ovf0) { exact16(tile, x20, y20, z20, c0, buf0); cnt0 = 16; }
    if (ovf1) { exact16(tile, x21, y21, z21, c0, buf1); cnt1 = 16; }

    {
        const int qg = b*NPTS + i0;
        g_scnt[qg*NPART + quarter] = cnt0;
        u64* dst = g_sbuf + (long long)(qg*NPART + quarter)*CAP;
        for (int t = 0; t < cnt0; t++) dst[t] = buf0[t];
    }
    {
        const int qg = b*NPTS + i1;
        g_scnt[qg*NPART + quarter] = cnt1;
        u64* dst = g_sbuf + (long long)(qg*NPART + quarter)*CAP;
        for (int t = 0; t < cnt1; t++) dst[t] = buf1[t];
    }
}

__global__ __launch_bounds__(256) void knn_merge()
{
    const int q = blockIdx.x*256 + threadIdx.x;
    float bd[16]; int bj[16];
#pragma unroll
    for (int t = 0; t < 16; t++) { bd[t] = 3.4e38f; bj[t] = 0; }
    float cm = 3.4e38f;
#pragma unroll
    for (int h = 0; h < NPART; h++) {
        const int c = g_scnt[q*NPART + h];
        const u64* src = g_sbuf + (long long)(q*NPART + h)*CAP;
        for (int e = 0; e < c; e++) {
            float2 v = up2(src[e]);
            float d = v.x;
            if (d < cm) {
                int am = 0; float mv = bd[0];
#pragma unroll
                for (int u = 1; u < 16; u++) if (bd[u] > mv) { mv = bd[u]; am = u; }
#pragma unroll
                for (int u = 0; u < 16; u++) if (u == am) { bd[u] = d; bj[u] = __float_as_int(v.y); }
                cm = bd[0];
#pragma unroll
                for (int u = 1; u < 16; u++) cm = fmaxf(cm, bd[u]);
            }
        }
    }
#pragma unroll
    for (int t = 0; t < 16; t++) g_idx[q*16 + t] = bj[t];
}

// =====================================================================
// Fused kernel: 64-pos tile, 128 threads, FOUR CTAs/SM.
// smem (floats): SA 0, SB 4096, SC 8192, SW 12288 (1024), SX1 13312 (256)
// =====================================================================
#define SA    0
#define SB    4096
#define SC    8192
#define SW    12288
#define SX1   13312
#define SMEM_FLOATS 13568   // 54272 B -> 4 CTAs/SM

// A-type chunk: 64 outs x 16 k (1024 floats, stride 64)
template<int KFULL>
__device__ __forceinline__ void ldgA16(float4 r[2], const float* __restrict__ src,
                                       int koff, int tid)
{
#pragma unroll
    for (int it = 0; it < 2; it++) {
        int l = it*128 + tid;
        int o = l & 63, k4 = l >> 6;
        r[it] = *(const float4*)(src + o*KFULL + koff + 4*k4);
    }
}
__device__ __forceinline__ void stsA16(float* __restrict__ dst, const float4 r[2], int tid)
{
#pragma unroll
    for (int it = 0; it < 2; it++) {
        int l = it*128 + tid;
        int o = l & 63, k = (l >> 6)*4;
        dst[(k  )*64+o] = r[it].x; dst[(k+1)*64+o] = r[it].y;
        dst[(k+2)*64+o] = r[it].z; dst[(k+3)*64+o] = r[it].w;
    }
}
// B-type chunk: 128 outs x 8 k (1024 floats, stride 128)
template<int KFULL>
__device__ __forceinline__ void ldgB8(float4 r[2], const float* __restrict__ src,
                                      int koff, int tid)
{
#pragma unroll
    for (int it = 0; it < 2; it++) {
        int l = it*128 + tid;
        int o = l & 127, k4 = l >> 7;
        r[it] = *(const float4*)(src + o*KFULL + koff + 4*k4);
    }
}
__device__ __forceinline__ void stsB8(float* __restrict__ dst, const float4 r[2], int tid)
{
#pragma unroll
    for (int it = 0; it < 2; it++) {
        int l = it*128 + tid;
        int o = l & 127, k = (l >> 7)*4;
        dst[(k  )*128+o] = r[it].x; dst[(k+1)*128+o] = r[it].y;
        dst[(k+2)*128+o] = r[it].z; dst[(k+3)*128+o] = r[it].w;
    }
}

// 8 out (4 pairs) x 4 pos, 16-k chunk. w stride 64, act stride 64.
__device__ __forceinline__ void gemm8c(const float* __restrict__ w,
                                       const float* __restrict__ a,
                                       int og, int pg, u64 acc[4][4])
{
#pragma unroll
    for (int k = 0; k < 16; k++) {
        const float* wr = w + k*64 + og*8;
        ulonglong2 w01 = *(const ulonglong2*)wr;
        ulonglong2 w23 = *(const ulonglong2*)(wr+4);
        u64 wp[4] = {w01.x,w01.y,w23.x,w23.y};
        float4 av = *(const float4*)(a + k*64 + pg*4);
        u64 as[4] = {pk2(av.x,av.x), pk2(av.y,av.y), pk2(av.z,av.z), pk2(av.w,av.w)};
#pragma unroll
        for (int op = 0; op < 4; op++)
#pragma unroll
            for (int p = 0; p < 4; p++) fma2(acc[op][p], wp[op], as[p]);
    }
}

// 16 out (8 pairs) x 4 pos, 8-k chunk. w stride 128, act stride 64.
__device__ __forceinline__ void gemm16c(const float* __restrict__ w,
                                        const float* __restrict__ a,
                                        int og, int pg, u64 acc[8][4])
{
#pragma unroll
    for (int k = 0; k < 8; k++) {
        const float* wr = w + k*128 + og*16;
        ulonglong2 w01 = *(const ulonglong2*)wr;
        ulonglong2 w23 = *(const ulonglong2*)(wr+4);
        ulonglong2 w45 = *(const ulonglong2*)(wr+8);
        ulonglong2 w67 = *(const ulonglong2*)(wr+12);
        u64 wp[8] = {w01.x,w01.y,w23.x,w23.y,w45.x,w45.y,w67.x,w67.y};
        float4 av = *(const float4*)(a + k*64 + pg*4);
        u64 as[4] = {pk2(av.x,av.x), pk2(av.y,av.y), pk2(av.z,av.z), pk2(av.w,av.w)};
#pragma unroll
        for (int op = 0; op < 8; op++)
#pragma unroll
            for (int p = 0; p < 4; p++) fma2(acc[op][p], wp[op], as[p]);
    }
}

__global__ void __launch_bounds__(128,4) fused_kernel(
    const float* __restrict__ xyz,
    const float* __restrict__ w1sc, const float* __restrict__ b1sc,
    const float* __restrict__ w1a,  const float* __restrict__ b1a,
    const float* __restrict__ w1b,  const float* __restrict__ b1b,
    const float* __restrict__ w1c,  const float* __restrict__ b1c,
    const float* __restrict__ w2sc, const float* __restrict__ b2sc,
    const float* __restrict__ w2a,  const float* __restrict__ b2a,
    const float* __restrict__ w2b,  const float* __restrict__ b2b,
    const float* __restrict__ w2c,  const float* __restrict__ b2c,
    float* __restrict__ outp)
{
    extern __shared__ float sm[];
    const int tid = threadIdx.x;
    const int pg = tid & 15, og = tid >> 4;
    const int base = blockIdx.x << 6;
    const int b  = base >> 17;
    const int n0 = (base & (NPTS*KNB - 1)) >> 4;
    const int nl = pg >> 2;

    float4 R[2];

    // ---- prologue ----
    ldgA16<64>(R, w1b, 0, tid);
    for (int l = tid; l < 640; l += 128) {
        int o = l/10, k = l - o*10;
        sm[SC + 640  + k*64 + o] = w1sc[l];
        sm[SC + 1280 + k*64 + o] = w1a[l];
    }
    if (tid < 64) {
        int nn = n0 + (tid >> 4);
        const float* xb = xyz + b*3*NPTS;
        int j = g_idx[(b*NPTS + nn)*KNB + (tid & 15)];
        float cx = xb[nn], cy = xb[NPTS+nn], cz = xb[2*NPTS+nn];
        float nx = xb[j],  ny = xb[NPTS+j],  nz = xb[2*NPTS+j];
        float rx = nx-cx, ry = ny-cy, rz = nz-cz;
        float dd = sqrtf(fmaf(rx,rx, fmaf(ry,ry, rz*rz)) + 1e-12f);
        sm[SC+0*64+tid]=cx; sm[SC+1*64+tid]=cy; sm[SC+2*64+tid]=cz;
        sm[SC+3*64+tid]=nx; sm[SC+4*64+tid]=ny; sm[SC+5*64+tid]=nz;
        sm[SC+6*64+tid]=rx; sm[SC+7*64+tid]=ry; sm[SC+8*64+tid]=rz;
        sm[SC+9*64+tid]=dd;
    }
    __syncthreads();
    stsA16(sm + SW, R, tid);
    ldgA16<64>(R, w1b, 16, tid);

    // ---- P1: stage1 sc + a (K=10) ; h->SA (leaky+b1a), sc->SB raw ----
    {
        u64 accS[4][4], accA[4][4];
#pragma unroll
        for (int op=0;op<4;op++)
#pragma unroll
            for (int p=0;p<4;p++) { accS[op][p]=0ull; accA[op][p]=0ull; }
#pragma unroll
        for (int k = 0; k < 10; k++) {
            const float* wsr = sm + SC + 640  + k*64 + og*8;
            const float* war = sm + SC + 1280 + k*64 + og*8;
            ulonglong2 ws01 = *(const ulonglong2*)wsr;
            ulonglong2 ws23 = *(const ulonglong2*)(wsr+4);
            ulonglong2 wa01 = *(const ulonglong2*)war;
            ulonglong2 wa23 = *(const ulonglong2*)(war+4);
            u64 wsp[4] = {ws01.x,ws01.y,ws23.x,ws23.y};
            u64 wap[4] = {wa01.x,wa01.y,wa23.x,wa23.y};
            float4 av = *(const float4*)(sm + SC + k*64 + pg*4);
            u64 as[4] = {pk2(av.x,av.x), pk2(av.y,av.y), pk2(av.z,av.z), pk2(av.w,av.w)};
#pragma unroll
            for (int op=0;op<4;op++)
#pragma unroll
                for (int p=0;p<4;p++) { fma2(accS[op][p], wsp[op], as[p]); fma2(accA[op][p], wap[op], as[p]); }
        }
#pragma unroll
        for (int op=0;op<4;op++) {
            int o0 = og*8 + 2*op;
            float ba0 = __ldg(b1a + o0), ba1 = __ldg(b1a + o0 + 1);
#pragma unroll
            for (int p=0;p<4;p++) {
                float2 va = up2(accA[op][p]);
                sm[SA + (o0  )*64 + pg*4 + p] = leaky(va.x + ba0);
                sm[SA + (o0+1)*64 + pg*4 + p] = leaky(va.y + ba1);
                float2 vs = up2(accS[op][p]);
                sm[SB + (o0  )*64 + pg*4 + p] = vs.x;
                sm[SB + (o0+1)*64 + pg*4 + p] = vs.y;
            }
        }
    }
    __syncthreads();

    u64 acc4[4][4];
#define ZERO4 {_Pragma("unroll") for (int op=0;op<4;op++) _Pragma("unroll") for (int p=0;p<4;p++) acc4[op][p]=0ull;}
#define PUMP(STSF)  { __syncthreads(); STSF(sm + SW, R, tid); __syncthreads(); }

    // ---- G1: stage1-b (w1b, 4 chunks) on SA(h) ; h2 -> SC ----
    ZERO4
#pragma unroll 1
    for (int c = 0; c < 3; c++) {
        // SW holds chunk c (chunk c+1 already in R for c==0)
        if (c > 0) ldgA16<64>(R, w1b, (c+1)*16, tid);
        gemm8c(sm + SW, sm + SA + c*1024, og, pg, acc4);
        PUMP(stsA16)
    }
    ldgA16<64>(R, w1c, 0, tid);
    gemm8c(sm + SW, sm + SA + 3*1024, og, pg, acc4);
    PUMP(stsA16)
#pragma unroll
    for (int op=0;op<4;op++) {
        int o0 = og*8 + 2*op;
        float b0 = __ldg(b1b + o0), b1 = __ldg(b1b + o0 + 1);
#pragma unroll
        for (int p=0;p<4;p++) {
            float2 v = up2(acc4[op][p]);
            sm[SC + (o0  )*64 + pg*4 + p] = leaky(v.x + b0);
            sm[SC + (o0+1)*64 + pg*4 + p] = leaky(v.y + b1);
        }
    }
    __syncthreads();

    // ---- G2: stage1-c (w1c, 4 chunks) on SC ; out1 -> SB ; x1 ----
    ZERO4
#pragma unroll 1
    for (int c = 0; c < 3; c++) {
        ldgA16<64>(R, w1c, (c+1)*16, tid);
        gemm8c(sm + SW, sm + SC + c*1024, og, pg, acc4);
        PUMP(stsA16)
    }
    ldgA16<128>(R, w2a, 0, tid);
    gemm8c(sm + SW, sm + SC + 3*1024, og, pg, acc4);
    PUMP(stsA16)
#pragma unroll
    for (int op=0;op<4;op++) {
        int o0 = og*8 + 2*op;
        float bt0 = __ldg(b1c + o0)     + __ldg(b1sc + o0);
        float bt1 = __ldg(b1c + o0 + 1) + __ldg(b1sc + o0 + 1);
        float v0m = -3.4e38f, v1m = -3.4e38f;
#pragma unroll
        for (int p=0;p<4;p++) {
            float2 v = up2(acc4[op][p]);
            float o0v = v.x + sm[SB + (o0  )*64 + pg*4 + p] + bt0;
            float o1v = v.y + sm[SB + (o0+1)*64 + pg*4 + p] + bt1;
            sm[SB + (o0  )*64 + pg*4 + p] = o0v;
            sm[SB + (o0+1)*64 + pg*4 + p] = o1v;
            v0m = fmaxf(v0m, o0v); v1m = fmaxf(v1m, o1v);
        }
        v0m = fmaxf(v0m, __shfl_xor_sync(0xffffffffu, v0m, 1));
        v0m = fmaxf(v0m, __shfl_xor_sync(0xffffffffu, v0m, 2));
        v1m = fmaxf(v1m, __shfl_xor_sync(0xffffffffu, v1m, 1));
        v1m = fmaxf(v1m, __shfl_xor_sync(0xffffffffu, v1m, 2));
        if ((pg & 3) == 0) {
            sm[SX1 + (o0  )*4 + nl] = v0m;
            sm[SX1 + (o0+1)*4 + nl] = v1m;
        }
    }
    __syncthreads();

    // ---- G3: stage2-a main (w2a k0..63, 4 chunks) on SB(out1) ----
    ZERO4
#pragma unroll 1
    for (int c = 0; c < 3; c++) {
        ldgA16<128>(R, w2a, (c+1)*16, tid);
        gemm8c(sm + SW, sm + SB + c*1024, og, pg, acc4);
        PUMP(stsA16)
    }
    ldgA16<128>(R, w2a, 64, tid);
    gemm8c(sm + SW, sm + SB + 3*1024, og, pg, acc4);
    PUMP(stsA16)

    // ---- G4: stage2-a x1-corr (w2a k64..127, 4 chunks of 16 cols) ----
    u64 crA[4] = {0,0,0,0};
#pragma unroll 1
    for (int c = 0; c < 3; c++) {
        ldgA16<128>(R, w2a, 64 + (c+1)*16, tid);
#pragma unroll
        for (int cc = 0; cc < 16; cc++) {
            const float* wr = sm + SW + cc*64 + og*8;
            ulonglong2 w01 = *(const ulonglong2*)wr;
            ulonglong2 w23 = *(const ulonglong2*)(wr+4);
            float xv = sm[SX1 + (c*16+cc)*4 + nl];
            u64 xs = pk2(xv, xv);
            fma2(crA[0], w01.x, xs); fma2(crA[1], w01.y, xs);
            fma2(crA[2], w23.x, xs); fma2(crA[3], w23.y, xs);
        }
        PUMP(stsA16)
    }
    ldgB8<64>(R, w2b, 0, tid);
#pragma unroll
    for (int cc = 0; cc < 16; cc++) {
        const float* wr = sm + SW + cc*64 + og*8;
        ulonglong2 w01 = *(const ulonglong2*)wr;
        ulonglong2 w23 = *(const ulonglong2*)(wr+4);
        float xv = sm[SX1 + (48+cc)*4 + nl];
        u64 xs = pk2(xv, xv);
        fma2(crA[0], w01.x, xs); fma2(crA[1], w01.y, xs);
        fma2(crA[2], w23.x, xs); fma2(crA[3], w23.y, xs);
    }
    PUMP(stsB8)
    // epilogue: h = leaky(main + corr + b2a) -> SA
#pragma unroll
    for (int op=0;op<4;op++) {
        int o0 = og*8 + 2*op;
        float2 c2 = up2(crA[op]);
        float b0 = __ldg(b2a + o0) + c2.x;
        float b1 = __ldg(b2a + o0 + 1) + c2.y;
#pragma unroll
        for (int p=0;p<4;p++) {
            float2 v = up2(acc4[op][p]);
            sm[SA + (o0  )*64 + pg*4 + p] = leaky(v.x + b0);
            sm[SA + (o0+1)*64 + pg*4 + p] = leaky(v.y + b1);
        }
    }
    __syncthreads();

    // ---- G5: stage2-b (w2b, 8 chunks) on SA(h) ; h2 -> SA/SC ----
    u64 acc[8][4];
#pragma unroll
    for (int op=0;op<8;op++)
#pragma unroll
        for (int p=0;p<4;p++) acc[op][p]=0ull;
#pragma unroll 1
    for (int c = 0; c < 7; c++) {
        ldgB8<64>(R, w2b, (c+1)*8, tid);
        gemm16c(sm + SW, sm + SA + c*512, og, pg, acc);
        PUMP(stsB8)
    }
    ldgB8<128>(R, w2c, 0, tid);
    gemm16c(sm + SW, sm + SA + 7*512, og, pg, acc);
    PUMP(stsB8)
#pragma unroll
    for (int op=0;op<8;op++) {
        int o0 = og*16 + 2*op;
        float b0 = __ldg(b2b + o0), b1 = __ldg(b2b + o0+1);
        float* d0 = sm + ((o0 < 64) ? (SA + o0*64) : (SC + (o0-64)*64));
        float* d1 = sm + ((o0+1 < 64) ? (SA + (o0+1)*64) : (SC + (o0+1-64)*64));
#pragma unroll
        for (int p=0;p<4;p++) {
            float2 v = up2(acc[op][p]);
            d0[pg*4 + p] = leaky(v.x + b0);
            d1[pg*4 + p] = leaky(v.y + b1);
        }
    }
    __syncthreads();

    // ---- G6: stage2-c (w2c, 16 chunks) on SA(h2 lo)/SC(h2 hi) ----
#pragma unroll
    for (int op=0;op<8;op++)
#pragma unroll
        for (int p=0;p<4;p++) acc[op][p]=0ull;
#pragma unroll 1
    for (int c = 0; c < 15; c++) {
        ldgB8<128>(R, w2c, (c+1)*8, tid);
        const float* act = (c < 8) ? (sm + SA + c*512) : (sm + SC + (c-8)*512);
        gemm16c(sm + SW, act, og, pg, acc);
        PUMP(stsB8)
    }
    ldgB8<128>(R, w2sc, 0, tid);
    gemm16c(sm + SW, sm + SC + 7*512, og, pg, acc);
    PUMP(stsB8)

    // ---- G7: sc main (w2sc k0..63, 8 chunks) on SB(out1) ----
#pragma unroll 1
    for (int c = 0; c < 7; c++) {
        ldgB8<128>(R, w2sc, (c+1)*8, tid);
        gemm16c(sm + SW, sm + SB + c*512, og, pg, acc);
        PUMP(stsB8)
    }
    ldgB8<128>(R, w2sc, 64, tid);
    gemm16c(sm + SW, sm + SB + 7*512, og, pg, acc);
    PUMP(stsB8)

    // ---- G8: sc x1-corr (w2sc k64..127, 8 chunks of 8 cols) ----
    u64 cr2[8] = {0,0,0,0,0,0,0,0};
#pragma unroll 1
    for (int c = 0; c < 7; c++) {
        ldgB8<128>(R, w2sc, 64 + (c+1)*8, tid);
#pragma unroll
        for (int cc = 0; cc < 8; cc++) {
            const float* wr = sm + SW + cc*128 + og*16;
            ulonglong2 w01 = *(const ulonglong2*)wr;
            ulonglong2 w23 = *(const ulonglong2*)(wr+4);
            ulonglong2 w45 = *(const ulonglong2*)(wr+8);
            ulonglong2 w67 = *(const ulonglong2*)(wr+12);
            float xv = sm[SX1 + (c*8+cc)*4 + nl];
            u64 xs = pk2(xv, xv);
            fma2(cr2[0], w01.x, xs); fma2(cr2[1], w01.y, xs);
            fma2(cr2[2], w23.x, xs); fma2(cr2[3], w23.y, xs);
            fma2(cr2[4], w45.x, xs); fma2(cr2[5], w45.y, xs);
            fma2(cr2[6], w67.x, xs); fma2(cr2[7], w67.y, xs);
        }
        PUMP(stsB8)
    }
#pragma unroll
    for (int cc = 0; cc < 8; cc++) {
        const float* wr = sm + SW + cc*128 + og*16;
        ulonglong2 w01 = *(const ulonglong2*)wr;
        ulonglong2 w23 = *(const ulonglong2*)(wr+4);
        ulonglong2 w45 = *(const ulonglong2*)(wr+8);
        ulonglong2 w67 = *(const ulonglong2*)(wr+12);
        float xv = sm[SX1 + (56+cc)*4 + nl];
        u64 xs = pk2(xv, xv);
        fma2(cr2[0], w01.x, xs); fma2(cr2[1], w01.y, xs);
        fma2(cr2[2], w23.x, xs); fma2(cr2[3], w23.y, xs);
        fma2(cr2[4], w45.x, xs); fma2(cr2[5], w45.y, xs);
        fma2(cr2[6], w67.x, xs); fma2(cr2[7], w67.y, xs);
    }

    // ---- final epilogue ----
#pragma unroll
    for (int op=0;op<8;op++) {
        int o0 = og*16 + 2*op;
        float2 c2 = up2(cr2[op]);
        float bt0 = __ldg(b2sc + o0)     + __ldg(b2c + o0)     + c2.x;
        float bt1 = __ldg(b2sc + o0 + 1) + __ldg(b2c + o0 + 1) + c2.y;
        float m0 = -3.4e38f, m1 = -3.4e38f;
#pragma unroll
        for (int p=0;p<4;p++) {
            float2 v = up2(acc[op][p]);
            m0 = fmaxf(m0, v.x); m1 = fmaxf(m1, v.y);
        }
        m0 += bt0; m1 += bt1;
        m0 = fmaxf(m0, __shfl_xor_sync(0xffffffffu, m0, 1));
        m0 = fmaxf(m0, __shfl_xor_sync(0xffffffffu, m0, 2));
        m1 = fmaxf(m1, __shfl_xor_sync(0xffffffffu, m1, 1));
        m1 = fmaxf(m1, __shfl_xor_sync(0xffffffffu, m1, 2));
        if ((pg & 3) == 0) {
            outp[((long long)b*128 + o0    )*NPTS + n0 + nl] = m0;
            outp[((long long)b*128 + o0 + 1)*NPTS + n0 + nl] = m1;
        }
    }
}

// =====================================================================
extern "C" void kernel_launch(void* const* d_in, const int* in_sizes, int n_in,
                              void* d_out, int out_size)
{
    const float* xyz     = (const float*)d_in[0];
    const float* p1_sc_w = (const float*)d_in[1];
    const float* p1_sc_b = (const float*)d_in[2];
    const float* p1_a_w  = (const float*)d_in[3];
    const float* p1_a_b  = (const float*)d_in[4];
    const float* p1_b_w  = (const float*)d_in[5];
    const float* p1_b_b  = (const float*)d_in[6];
    const float* p1_c_w  = (const float*)d_in[7];
    const float* p1_c_b  = (const float*)d_in[8];
    const float* p2_sc_w = (const float*)d_in[9];
    const float* p2_sc_b = (const float*)d_in[10];
    const float* p2_a_w  = (const float*)d_in[11];
    const float* p2_a_b  = (const float*)d_in[12];
    const float* p2_b_w  = (const float*)d_in[13];
    const float* p2_b_b  = (const float*)d_in[14];
    const float* p2_c_w  = (const float*)d_in[15];
    const float* p2_c_b  = (const float*)d_in[16];
    float* outp = (float*)d_out;

    cudaFuncSetAttribute(fused_kernel, cudaFuncAttributeMaxDynamicSharedMemorySize,
                         SMEM_FLOATS*4);

    knn_part<<<512, 128, 32768>>>(xyz);
    knn_merge<<<NQ/256, 256>>>();
    fused_kernel<<<NPOS/64, 128, SMEM_FLOATS*4>>>(
        xyz,
        p1_sc_w, p1_sc_b, p1_a_w, p1_a_b, p1_b_w, p1_b_b, p1_c_w, p1_c_b,
        p2_sc_w, p2_sc_b, p2_a_w, p2_a_b, p2_b_w, p2_b_b, p2_c_w, p2_c_b,
        outp);
}

// round 11
// speedup vs baseline: 1.2226x; 1.0622x over previous
#include <cuda_runtime.h>
#include <math.h>

#define BATCH 4
#define NPTS  8192
#define KNB   16
#define NPOS  (BATCH*NPTS*KNB)   // 524288
#define NQ    (BATCH*NPTS)       // 32768
#define CAP   48
#define NPART 4

__device__ int g_idx[NQ*KNB];
__device__ unsigned long long g_sbuf[(long long)NQ*NPART*CAP];
__device__ int g_scnt[NQ*NPART];
__device__ float g_out1[(long long)NPOS*64];   // 134 MB
__device__ float g_x1[(long long)NQ*64];       // 8 MB

typedef unsigned long long u64;

__device__ __forceinline__ u64 pk2(float x, float y) {
    u64 r; asm("mov.b64 %0,{%1,%2};" : "=l"(r) : "f"(x), "f"(y)); return r;
}
__device__ __forceinline__ float2 up2(u64 v) {
    float2 r; asm("mov.b64 {%0,%1},%2;" : "=f"(r.x), "=f"(r.y) : "l"(v)); return r;
}
__device__ __forceinline__ void fma2(u64& d, u64 a, u64 b) {
    asm("fma.rn.f32x2 %0,%1,%2,%0;" : "+l"(d) : "l"(a), "l"(b));
}
__device__ __forceinline__ float leaky(float v) { return v >= 0.f ? v : 0.2f*v; }

// =====================================================================
// KNN (unchanged from R9/R10)
// =====================================================================
__device__ __forceinline__ void bitonic32(float s[32]) {
#pragma unroll
    for (int k = 2; k <= 32; k <<= 1) {
#pragma unroll
        for (int j = k >> 1; j > 0; j >>= 1) {
#pragma unroll
            for (int ii = 0; ii < 32; ii++) {
                int l = ii ^ j;
                if (l > ii) {
                    float lo = fminf(s[ii], s[l]);
                    float hi = fmaxf(s[ii], s[l]);
                    bool up = ((ii & k) == 0);
                    s[ii] = up ? lo : hi;
                    s[l]  = up ? hi : lo;
                }
            }
        }
    }
}

__device__ __forceinline__ void exact16(const float4* tile, float x2, float y2,
                                        float z2, int c0, u64 buf[16]) {
    float bd[16]; int bj[16];
#pragma unroll
    for (int t = 0; t < 16; t++) { bd[t] = 3.4e38f; bj[t] = 0; }
    float cm = 3.4e38f;
    for (int j = 0; j < 2048; j++) {
        float4 p = tile[j];
        float d = fmaf(x2, p.x, fmaf(y2, p.y, fmaf(z2, p.z, p.w)));
        if (d < cm) {
            int am = 0; float mv = bd[0];
#pragma unroll
            for (int u = 1; u < 16; u++) if (bd[u] > mv) { mv = bd[u]; am = u; }
#pragma unroll
            for (int u = 0; u < 16; u++) if (u == am) { bd[u] = d; bj[u] = c0 + j; }
            cm = bd[0];
#pragma unroll
            for (int u = 1; u < 16; u++) cm = fmaxf(cm, bd[u]);
        }
    }
#pragma unroll
    for (int t = 0; t < 16; t++) buf[t] = pk2(bd[t], __int_as_float(bj[t]));
}

__global__ __launch_bounds__(128) void knn_part(const float* __restrict__ xyz)
{
    extern __shared__ float4 tile[];
    const int tid = threadIdx.x;
    const int quarter = blockIdx.x & 3;
    const int qb = (blockIdx.x >> 2) & 31;
    const int b  = blockIdx.x >> 7;
    const int i0 = qb*256 + tid;
    const int i1 = i0 + 128;
    const float* xb = xyz + b*3*NPTS;
    const int c0 = quarter*2048;

    for (int l = tid; l < 512; l += 128) {
        float4 vx = ((const float4*)(xb + c0))[l];
        float4 vy = ((const float4*)(xb + NPTS + c0))[l];
        float4 vz = ((const float4*)(xb + 2*NPTS + c0))[l];
        tile[4*l+0] = make_float4(vx.x, vy.x, vz.x, fmaf(vx.x,vx.x, fmaf(vy.x,vy.x, vz.x*vz.x)));
        tile[4*l+1] = make_float4(vx.y, vy.y, vz.y, fmaf(vx.y,vx.y, fmaf(vy.y,vy.y, vz.y*vz.y)));
        tile[4*l+2] = make_float4(vx.z, vy.z, vz.z, fmaf(vx.z,vx.z, fmaf(vy.z,vy.z, vz.z*vz.z)));
        tile[4*l+3] = make_float4(vx.w, vy.w, vz.w, fmaf(vx.w,vx.w, fmaf(vy.w,vy.w, vz.w*vz.w)));
    }
    __syncthreads();

    const float x20 = -2.0f*xb[i0], y20 = -2.0f*xb[NPTS+i0], z20 = -2.0f*xb[2*NPTS+i0];
    const float x21 = -2.0f*xb[i1], y21 = -2.0f*xb[NPTS+i1], z21 = -2.0f*xb[2*NPTS+i1];

    float s0[32], s1[32];
#pragma unroll
    for (int t = 0; t < 32; t++) { s0[t] = 3.4e38f; s1[t] = 3.4e38f; }
    for (int j0 = 0; j0 < 2048; j0 += 32) {
#pragma unroll
        for (int u = 0; u < 32; u++) {
            float4 p = tile[j0+u];
            float d0 = fmaf(x20, p.x, fmaf(y20, p.y, fmaf(z20, p.z, p.w)));
            float d1 = fmaf(x21, p.x, fmaf(y21, p.y, fmaf(z21, p.z, p.w)));
            s0[u] = fminf(s0[u], d0);
            s1[u] = fminf(s1[u], d1);
        }
    }

    bitonic32(s0);
    bitonic32(s1);
    const float T0 = s0[15], T1 = s1[15];

    u64 buf0[CAP], buf1[CAP];
    int cnt0 = 0, cnt1 = 0, ovf0 = 0, ovf1 = 0;
    for (int j = 0; j < 2048; j++) {
        float4 p = tile[j];
        float d0 = fmaf(x20, p.x, fmaf(y20, p.y, fmaf(z20, p.z, p.w)));
        float d1 = fmaf(x21, p.x, fmaf(y21, p.y, fmaf(z21, p.z, p.w)));
        if (d0 <= T0) {
            if (cnt0 < CAP) { buf0[cnt0] = pk2(d0, __int_as_float(c0+j)); cnt0++; }
            else ovf0 = 1;
        }
        if (d1 <= T1) {
            if (cnt1 < CAP) { buf1[cnt1] = pk2(d1, __int_as_float(c0+j)); cnt1++; }
            else ovf1 = 1;
        }
    }

    if (ovf0) { exact16(tile, x20, y20, z20, c0, buf0); cnt0 = 16; }
    if (ovf1) { exact16(tile, x21, y21, z21, c0, buf1); cnt1 = 16; }

    {
        const int qg = b*NPTS + i0;
        g_scnt[qg*NPART + quarter] = cnt0;
        u64* dst = g_sbuf + (long long)(qg*NPART + quarter)*CAP;
        for (int t = 0; t < cnt0; t++) dst[t] = buf0[t];
    }
    {
        const int qg = b*NPTS + i1;
        g_scnt[qg*NPART + quarter] = cnt1;
        u64* dst = g_sbuf + (long long)(qg*NPART + quarter)*CAP;
        for (int t = 0; t < cnt1; t++) dst[t] = buf1[t];
    }
}

__global__ __launch_bounds__(256) void knn_merge()
{
    const int q = blockIdx.x*256 + threadIdx.x;
    float bd[16]; int bj[16];
#pragma unroll
    for (int t = 0; t < 16; t++) { bd[t] = 3.4e38f; bj[t] = 0; }
    float cm = 3.4e38f;
#pragma unroll
    for (int h = 0; h < NPART; h++) {
        const int c = g_scnt[q*NPART + h];
        const u64* src = g_sbuf + (long long)(q*NPART + h)*CAP;
        for (int e = 0; e < c; e++) {
            float2 v = up2(src[e]);
            float d = v.x;
            if (d < cm) {
                int am = 0; float mv = bd[0];
#pragma unroll
                for (int u = 1; u < 16; u++) if (bd[u] > mv) { mv = bd[u]; am = u; }
#pragma unroll
                for (int u = 0; u < 16; u++) if (u == am) { bd[u] = d; bj[u] = __float_as_int(v.y); }
                cm = bd[0];
#pragma unroll
                for (int u = 1; u < 16; u++) cm = fmaxf(cm, bd[u]);
            }
        }
    }
#pragma unroll
    for (int t = 0; t < 16; t++) g_idx[q*16 + t] = bj[t];
}

// =====================================================================
// Stage 1: 64-pos tiles, 128 thr, 4 CTAs/SM (R10 front half + store)
// smem: SA 0, SB 4096, SC 8192, SW 12288(1024) -> 13312 floats
// =====================================================================
#define S1A 0
#define S1B 4096
#define S1C 8192
#define S1W 12288
#define S1_FLOATS 13312

template<int KFULL>
__device__ __forceinline__ void ldgA16(float4 r[2], const float* __restrict__ src,
                                       int koff, int tid)
{
#pragma unroll
    for (int it = 0; it < 2; it++) {
        int l = it*128 + tid;
        int o = l & 63, k4 = l >> 6;
        r[it] = *(const float4*)(src + o*KFULL + koff + 4*k4);
    }
}
__device__ __forceinline__ void stsA16(float* __restrict__ dst, const float4 r[2], int tid)
{
#pragma unroll
    for (int it = 0; it < 2; it++) {
        int l = it*128 + tid;
        int o = l & 63, k = (l >> 6)*4;
        dst[(k  )*64+o] = r[it].x; dst[(k+1)*64+o] = r[it].y;
        dst[(k+2)*64+o] = r[it].z; dst[(k+3)*64+o] = r[it].w;
    }
}

// 8 out (4 pairs) x 4 pos, 16-k chunk. w stride 64, act stride 64.
__device__ __forceinline__ void gemm8c(const float* __restrict__ w,
                                       const float* __restrict__ a,
                                       int og, int pg, u64 acc[4][4])
{
#pragma unroll
    for (int k = 0; k < 16; k++) {
        const float* wr = w + k*64 + og*8;
        ulonglong2 w01 = *(const ulonglong2*)wr;
        ulonglong2 w23 = *(const ulonglong2*)(wr+4);
        u64 wp[4] = {w01.x,w01.y,w23.x,w23.y};
        float4 av = *(const float4*)(a + k*64 + pg*4);
        u64 as[4] = {pk2(av.x,av.x), pk2(av.y,av.y), pk2(av.z,av.z), pk2(av.w,av.w)};
#pragma unroll
        for (int op = 0; op < 4; op++)
#pragma unroll
            for (int p = 0; p < 4; p++) fma2(acc[op][p], wp[op], as[p]);
    }
}

__global__ void __launch_bounds__(128,4) stage1_kernel(
    const float* __restrict__ xyz,
    const float* __restrict__ w1sc, const float* __restrict__ b1sc,
    const float* __restrict__ w1a,  const float* __restrict__ b1a,
    const float* __restrict__ w1b,  const float* __restrict__ b1b,
    const float* __restrict__ w1c,  const float* __restrict__ b1c)
{
    extern __shared__ float sm[];
    const int tid = threadIdx.x;
    const int pg = tid & 15, og = tid >> 4;
    const int base = blockIdx.x << 6;
    const int b  = base >> 17;
    const int n0 = (base & (NPTS*KNB - 1)) >> 4;
    const int nl = pg >> 2;

    float4 R[2];

    // ---- prologue ----
    ldgA16<64>(R, w1b, 0, tid);
    for (int l = tid; l < 640; l += 128) {
        int o = l/10, k = l - o*10;
        sm[S1C + 640  + k*64 + o] = w1sc[l];
        sm[S1C + 1280 + k*64 + o] = w1a[l];
    }
    if (tid < 64) {
        int nn = n0 + (tid >> 4);
        const float* xb = xyz + b*3*NPTS;
        int j = g_idx[(b*NPTS + nn)*KNB + (tid & 15)];
        float cx = xb[nn], cy = xb[NPTS+nn], cz = xb[2*NPTS+nn];
        float nx = xb[j],  ny = xb[NPTS+j],  nz = xb[2*NPTS+j];
        float rx = nx-cx, ry = ny-cy, rz = nz-cz;
        float dd = sqrtf(fmaf(rx,rx, fmaf(ry,ry, rz*rz)) + 1e-12f);
        sm[S1C+0*64+tid]=cx; sm[S1C+1*64+tid]=cy; sm[S1C+2*64+tid]=cz;
        sm[S1C+3*64+tid]=nx; sm[S1C+4*64+tid]=ny; sm[S1C+5*64+tid]=nz;
        sm[S1C+6*64+tid]=rx; sm[S1C+7*64+tid]=ry; sm[S1C+8*64+tid]=rz;
        sm[S1C+9*64+tid]=dd;
    }
    __syncthreads();
    stsA16(sm + S1W, R, tid);
    ldgA16<64>(R, w1b, 16, tid);

    // ---- P1: stage1 sc + a (K=10) ; h->SA, sc->SB raw ----
    {
        u64 accS[4][4], accA[4][4];
#pragma unroll
        for (int op=0;op<4;op++)
#pragma unroll
            for (int p=0;p<4;p++) { accS[op][p]=0ull; accA[op][p]=0ull; }
#pragma unroll
        for (int k = 0; k < 10; k++) {
            const float* wsr = sm + S1C + 640  + k*64 + og*8;
            const float* war = sm + S1C + 1280 + k*64 + og*8;
            ulonglong2 ws01 = *(const ulonglong2*)wsr;
            ulonglong2 ws23 = *(const ulonglong2*)(wsr+4);
            ulonglong2 wa01 = *(const ulonglong2*)war;
            ulonglong2 wa23 = *(const ulonglong2*)(war+4);
            u64 wsp[4] = {ws01.x,ws01.y,ws23.x,ws23.y};
            u64 wap[4] = {wa01.x,wa01.y,wa23.x,wa23.y};
            float4 av = *(const float4*)(sm + S1C + k*64 + pg*4);
            u64 as[4] = {pk2(av.x,av.x), pk2(av.y,av.y), pk2(av.z,av.z), pk2(av.w,av.w)};
#pragma unroll
            for (int op=0;op<4;op++)
#pragma unroll
                for (int p=0;p<4;p++) { fma2(accS[op][p], wsp[op], as[p]); fma2(accA[op][p], wap[op], as[p]); }
        }
#pragma unroll
        for (int op=0;op<4;op++) {
            int o0 = og*8 + 2*op;
            float ba0 = __ldg(b1a + o0), ba1 = __ldg(b1a + o0 + 1);
#pragma unroll
            for (int p=0;p<4;p++) {
                float2 va = up2(accA[op][p]);
                sm[S1A + (o0  )*64 + pg*4 + p] = leaky(va.x + ba0);
                sm[S1A + (o0+1)*64 + pg*4 + p] = leaky(va.y + ba1);
                float2 vs = up2(accS[op][p]);
                sm[S1B + (o0  )*64 + pg*4 + p] = vs.x;
                sm[S1B + (o0+1)*64 + pg*4 + p] = vs.y;
            }
        }
    }
    __syncthreads();

    u64 acc4[4][4];
#define ZERO4 {_Pragma("unroll") for (int op=0;op<4;op++) _Pragma("unroll") for (int p=0;p<4;p++) acc4[op][p]=0ull;}
#define PUMP1(STSF)  { __syncthreads(); STSF(sm + S1W, R, tid); __syncthreads(); }

    // ---- G1: stage1-b (w1b, 4 chunks) on SA(h) ; h2 -> SC ----
    ZERO4
#pragma unroll 1
    for (int c = 0; c < 3; c++) {
        if (c > 0) ldgA16<64>(R, w1b, (c+1)*16, tid);
        gemm8c(sm + S1W, sm + S1A + c*1024, og, pg, acc4);
        PUMP1(stsA16)
    }
    ldgA16<64>(R, w1c, 0, tid);
    gemm8c(sm + S1W, sm + S1A + 3*1024, og, pg, acc4);
    PUMP1(stsA16)
#pragma unroll
    for (int op=0;op<4;op++) {
        int o0 = og*8 + 2*op;
        float b0 = __ldg(b1b + o0), b1 = __ldg(b1b + o0 + 1);
#pragma unroll
        for (int p=0;p<4;p++) {
            float2 v = up2(acc4[op][p]);
            sm[S1C + (o0  )*64 + pg*4 + p] = leaky(v.x + b0);
            sm[S1C + (o0+1)*64 + pg*4 + p] = leaky(v.y + b1);
        }
    }
    __syncthreads();

    // ---- G2: stage1-c (w1c, 4 chunks) on SC ; out1 -> SB ; x1 -> gmem ----
    ZERO4
#pragma unroll 1
    for (int c = 0; c < 3; c++) {
        ldgA16<64>(R, w1c, (c+1)*16, tid);
        gemm8c(sm + S1W, sm + S1C + c*1024, og, pg, acc4);
        PUMP1(stsA16)
    }
    gemm8c(sm + S1W, sm + S1C + 3*1024, og, pg, acc4);
#pragma unroll
    for (int op=0;op<4;op++) {
        int o0 = og*8 + 2*op;
        float bt0 = __ldg(b1c + o0)     + __ldg(b1sc + o0);
        float bt1 = __ldg(b1c + o0 + 1) + __ldg(b1sc + o0 + 1);
        float v0m = -3.4e38f, v1m = -3.4e38f;
#pragma unroll
        for (int p=0;p<4;p++) {
            float2 v = up2(acc4[op][p]);
            float o0v = v.x + sm[S1B + (o0  )*64 + pg*4 + p] + bt0;
            float o1v = v.y + sm[S1B + (o0+1)*64 + pg*4 + p] + bt1;
            sm[S1B + (o0  )*64 + pg*4 + p] = o0v;
            sm[S1B + (o0+1)*64 + pg*4 + p] = o1v;
            v0m = fmaxf(v0m, o0v); v1m = fmaxf(v1m, o1v);
        }
        v0m = fmaxf(v0m, __shfl_xor_sync(0xffffffffu, v0m, 1));
        v0m = fmaxf(v0m, __shfl_xor_sync(0xffffffffu, v0m, 2));
        v1m = fmaxf(v1m, __shfl_xor_sync(0xffffffffu, v1m, 1));
        v1m = fmaxf(v1m, __shfl_xor_sync(0xffffffffu, v1m, 2));
        if ((pg & 3) == 0) {
            long long q = (long long)(b*NPTS + n0 + nl);
            g_x1[q*64 + o0]     = v0m;
            g_x1[q*64 + o0 + 1] = v1m;
        }
    }
    __syncthreads();
    // store out1 tile (coalesced float4)
    for (int l = tid; l < 1024; l += 128)
        ((float4*)(g_out1 + (long long)blockIdx.x*4096))[l] = ((const float4*)(sm + S1B))[l];
}

// =====================================================================
// Stage 2: 128-pos tiles, 256 thr (og=warp 0..7, pg=lane 0..31), 2 CTAs/SM
// smem: B1 0 (8192 out1->), B2 8192 (h->h2 hi), B3 16384 (h2 lo),
//       SW 24576 (1024), SX 25600 (512) -> 26112 floats = 104448 B
// =====================================================================
#define T2B1 0
#define T2B2 8192
#define T2B3 16384
#define T2SW 24576
#define T2SX 25600
#define T2_FLOATS 26112

template<int KFULL>
__device__ __forceinline__ void ldgA2(float4& r, const float* __restrict__ src,
                                      int koff, int tid)
{
    int o = tid & 63, k4 = tid >> 6;
    r = *(const float4*)(src + o*KFULL + koff + 4*k4);
}
__device__ __forceinline__ void stsA2(float* __restrict__ dst, const float4& r, int tid)
{
    int o = tid & 63, k = (tid >> 6)*4;
    dst[(k  )*64+o] = r.x; dst[(k+1)*64+o] = r.y;
    dst[(k+2)*64+o] = r.z; dst[(k+3)*64+o] = r.w;
}
template<int KFULL>
__device__ __forceinline__ void ldgB2(float4& r, const float* __restrict__ src,
                                      int koff, int tid)
{
    int o = tid & 127, k4 = tid >> 7;
    r = *(const float4*)(src + o*KFULL + koff + 4*k4);
}
__device__ __forceinline__ void stsB2(float* __restrict__ dst, const float4& r, int tid)
{
    int o = tid & 127, k = (tid >> 7)*4;
    dst[(k  )*128+o] = r.x; dst[(k+1)*128+o] = r.y;
    dst[(k+2)*128+o] = r.z; dst[(k+3)*128+o] = r.w;
}

// 8 out (4 pairs) x 4 pos, 16-k chunk. w stride 64, act stride 128.
__device__ __forceinline__ void gemm8d(const float* __restrict__ w,
                                       const float* __restrict__ a,
                                       int og, int pg, u64 acc[4][4])
{
#pragma unroll
    for (int k = 0; k < 16; k++) {
        const float* wr = w + k*64 + og*8;
        ulonglong2 w01 = *(const ulonglong2*)wr;
        ulonglong2 w23 = *(const ulonglong2*)(wr+4);
        u64 wp[4] = {w01.x,w01.y,w23.x,w23.y};
        float4 av = *(const float4*)(a + k*128 + pg*4);
        u64 as[4] = {pk2(av.x,av.x), pk2(av.y,av.y), pk2(av.z,av.z), pk2(av.w,av.w)};
#pragma unroll
        for (int op = 0; op < 4; op++)
#pragma unroll
            for (int p = 0; p < 4; p++) fma2(acc[op][p], wp[op], as[p]);
    }
}

// 16 out (8 pairs) x 4 pos, 8-k chunk. w stride 128, act stride 128.
__device__ __forceinline__ void gemm16d(const float* __restrict__ w,
                                        const float* __restrict__ a,
                                        int og, int pg, u64 acc[8][4])
{
#pragma unroll
    for (int k = 0; k < 8; k++) {
        const float* wr = w + k*128 + og*16;
        ulonglong2 w01 = *(const ulonglong2*)wr;
        ulonglong2 w23 = *(const ulonglong2*)(wr+4);
        ulonglong2 w45 = *(const ulonglong2*)(wr+8);
        ulonglong2 w67 = *(const ulonglong2*)(wr+12);
        u64 wp[8] = {w01.x,w01.y,w23.x,w23.y,w45.x,w45.y,w67.x,w67.y};
        float4 av = *(const float4*)(a + k*128 + pg*4);
        u64 as[4] = {pk2(av.x,av.x), pk2(av.y,av.y), pk2(av.z,av.z), pk2(av.w,av.w)};
#pragma unroll
        for (int op = 0; op < 8; op++)
#pragma unroll
            for (int p = 0; p < 4; p++) fma2(acc[op][p], wp[op], as[p]);
    }
}

__global__ void __launch_bounds__(256,2) stage2_kernel(
    const float* __restrict__ w2sc, const float* __restrict__ b2sc,
    const float* __restrict__ w2a,  const float* __restrict__ b2a,
    const float* __restrict__ w2b,  const float* __restrict__ b2b,
    const float* __restrict__ w2c,  const float* __restrict__ b2c,
    float* __restrict__ outp)
{
    extern __shared__ float sm[];
    const int tid = threadIdx.x;
    const int og = tid >> 5, pg = tid & 31;
    const int nl = pg >> 2;
    const int base = blockIdx.x << 7;             // 128 pos
    const int b  = base >> 17;
    const int nb = (base & (NPTS*KNB - 1)) >> 4;  // first of 8 n

    float4 R;

    // ---- prologue: load out1 (2 stage1 tiles) + x1 ; prefetch w2a c0 ----
    ldgA2<128>(R, w2a, 0, tid);
    {
        const float4* src = (const float4*)(g_out1 + (long long)blockIdx.x*8192);
        for (int l = tid; l < 2048; l += 256) {
            int t = l >> 10, i = l & 1023;
            int ch = i >> 4, p4 = i & 15;
            *(float4*)(sm + T2B1 + ch*128 + t*64 + p4*4) = src[l];
        }
    }
    for (int l = tid; l < 512; l += 256) {
        int ch = l >> 3, nn = l & 7;
        sm[T2SX + ch*8 + nn] = g_x1[(long long)(b*NPTS + nb + nn)*64 + ch];
    }
    __syncthreads();
    stsA2(sm + T2SW, R, tid);
    ldgA2<128>(R, w2a, 16, tid);
    __syncthreads();

    u64 acc4[4][4];
#define ZERO4B {_Pragma("unroll") for (int op=0;op<4;op++) _Pragma("unroll") for (int p=0;p<4;p++) acc4[op][p]=0ull;}
#define PUMP2(STSF)  { __syncthreads(); STSF(sm + T2SW, R, tid); __syncthreads(); }

    // ---- a main (w2a k0..63, 4 chunks) on B1(out1) ----
    ZERO4B
    gemm8d(sm + T2SW, sm + T2B1, og, pg, acc4);
    PUMP2(stsA2)
    ldgA2<128>(R, w2a, 32, tid);
    gemm8d(sm + T2SW, sm + T2B1 + 16*128, og, pg, acc4);
    PUMP2(stsA2)
    ldgA2<128>(R, w2a, 48, tid);
    gemm8d(sm + T2SW, sm + T2B1 + 32*128, og, pg, acc4);
    PUMP2(stsA2)
    ldgA2<128>(R, w2a, 64, tid);
    gemm8d(sm + T2SW, sm + T2B1 + 48*128, og, pg, acc4);
    PUMP2(stsA2)

    // ---- a x1-corr (w2a k64..127, 4 chunks of 16 cols) ----
    u64 crA[4] = {0,0,0,0};
#define CORRA(C0) \
    _Pragma("unroll") \
    for (int cc = 0; cc < 16; cc++) { \
        const float* wr = sm + T2SW + cc*64 + og*8; \
        ulonglong2 w01 = *(const ulonglong2*)wr; \
        ulonglong2 w23 = *(const ulonglong2*)(wr+4); \
        float xv = sm[T2SX + ((C0)+cc)*8 + nl]; \
        u64 xs = pk2(xv, xv); \
        fma2(crA[0], w01.x, xs); fma2(crA[1], w01.y, xs); \
        fma2(crA[2], w23.x, xs); fma2(crA[3], w23.y, xs); \
    }
    ldgA2<128>(R, w2a, 80, tid);
    CORRA(0)
    PUMP2(stsA2)
    ldgA2<128>(R, w2a, 96, tid);
    CORRA(16)
    PUMP2(stsA2)
    ldgA2<128>(R, w2a, 112, tid);
    CORRA(32)
    PUMP2(stsA2)
    ldgB2<64>(R, w2b, 0, tid);
    CORRA(48)
    PUMP2(stsB2)

    // ---- a epilogue: h -> B2 ----
#pragma unroll
    for (int op=0;op<4;op++) {
        int o0 = og*8 + 2*op;
        float2 c2 = up2(crA[op]);
        float b0 = __ldg(b2a + o0) + c2.x;
        float b1 = __ldg(b2a + o0 + 1) + c2.y;
#pragma unroll
        for (int p=0;p<4;p++) {
            float2 v = up2(acc4[op][p]);
            sm[T2B2 + (o0  )*128 + pg*4 + p] = leaky(v.x + b0);
            sm[T2B2 + (o0+1)*128 + pg*4 + p] = leaky(v.y + b1);
        }
    }
    __syncthreads();

    // ---- b (w2b, 8 chunks) on B2(h) ----
    u64 acc[8][4];
#pragma unroll
    for (int op=0;op<8;op++)
#pragma unroll
        for (int p=0;p<4;p++) acc[op][p]=0ull;
#pragma unroll 1
    for (int c = 0; c < 7; c++) {
        ldgB2<64>(R, w2b, (c+1)*8, tid);
        gemm16d(sm + T2SW, sm + T2B2 + c*8*128, og, pg, acc);
        PUMP2(stsB2)
    }
    ldgB2<128>(R, w2c, 0, tid);
    gemm16d(sm + T2SW, sm + T2B2 + 56*128, og, pg, acc);
    PUMP2(stsB2)
    // h2 epilogue: ch<64 -> B3, ch>=64 -> B2
#pragma unroll
    for (int op=0;op<8;op++) {
        int o0 = og*16 + 2*op;
        float b0 = __ldg(b2b + o0), b1 = __ldg(b2b + o0+1);
        float* d0 = sm + ((o0 < 64) ? (T2B3 + o0*128) : (T2B2 + (o0-64)*128));
        float* d1 = sm + ((o0+1 < 64) ? (T2B3 + (o0+1)*128) : (T2B2 + (o0+1-64)*128));
#pragma unroll
        for (int p=0;p<4;p++) {
            float2 v = up2(acc[op][p]);
            d0[pg*4 + p] = leaky(v.x + b0);
            d1[pg*4 + p] = leaky(v.y + b1);
        }
    }
    __syncthreads();

    // ---- c + sc into one accumulator ----
#pragma unroll
    for (int op=0;op<8;op++)
#pragma unroll
        for (int p=0;p<4;p++) acc[op][p]=0ull;
    // c lo (w2c k0..63) on B3
#pragma unroll 1
    for (int c = 0; c < 7; c++) {
        ldgB2<128>(R, w2c, (c+1)*8, tid);
        gemm16d(sm + T2SW, sm + T2B3 + c*8*128, og, pg, acc);
        PUMP2(stsB2)
    }
    ldgB2<128>(R, w2c, 64, tid);
    gemm16d(sm + T2SW, sm + T2B3 + 56*128, og, pg, acc);
    PUMP2(stsB2)
    // c hi (w2c k64..127) on B2
#pragma unroll 1
    for (int c = 0; c < 7; c++) {
        ldgB2<128>(R, w2c, 64 + (c+1)*8, tid);
        gemm16d(sm + T2SW, sm + T2B2 + c*8*128, og, pg, acc);
        PUMP2(stsB2)
    }
    ldgB2<128>(R, w2sc, 0, tid);
    gemm16d(sm + T2SW, sm + T2B2 + 56*128, og, pg, acc);
    PUMP2(stsB2)
    // sc main (w2sc k0..63) on B1(out1)
#pragma unroll 1
    for (int c = 0; c < 7; c++) {
        ldgB2<128>(R, w2sc, (c+1)*8, tid);
        gemm16d(sm + T2SW, sm + T2B1 + c*8*128, og, pg, acc);
        PUMP2(stsB2)
    }
    ldgB2<128>(R, w2sc, 64, tid);
    gemm16d(sm + T2SW, sm + T2B1 + 56*128, og, pg, acc);
    PUMP2(stsB2)

    // ---- sc x1-corr (w2sc k64..127, 8 chunks of 8 cols) ----
    u64 cr2[8] = {0,0,0,0,0,0,0,0};
#define CORRS(C0) \
    _Pragma("unroll") \
    for (int cc = 0; cc < 8; cc++) { \
        const float* wr = sm + T2SW + cc*128 + og*16; \
        ulonglong2 w01 = *(const ulonglong2*)wr; \
        ulonglong2 w23 = *(const ulonglong2*)(wr+4); \
        ulonglong2 w45 = *(const ulonglong2*)(wr+8); \
        ulonglong2 w67 = *(const ulonglong2*)(wr+12); \
        float xv = sm[T2SX + ((C0)+cc)*8 + nl]; \
        u64 xs = pk2(xv, xv); \
        fma2(cr2[0], w01.x, xs); fma2(cr2[1], w01.y, xs); \
        fma2(cr2[2], w23.x, xs); fma2(cr2[3], w23.y, xs); \
        fma2(cr2[4], w45.x, xs); fma2(cr2[5], w45.y, xs); \
        fma2(cr2[6], w67.x, xs); fma2(cr2[7], w67.y, xs); \
    }
#pragma unroll 1
    for (int c = 0; c < 7; c++) {
        ldgB2<128>(R, w2sc, 64 + (c+1)*8, tid);
        CORRS(c*8)
        PUMP2(stsB2)
    }
    CORRS(56)

    // ---- final epilogue ----
#pragma unroll
    for (int op=0;op<8;op++) {
        int o0 = og*16 + 2*op;
        float2 c2 = up2(cr2[op]);
        float bt0 = __ldg(b2sc + o0)     + __ldg(b2c + o0)     + c2.x;
        float bt1 = __ldg(b2sc + o0 + 1) + __ldg(b2c + o0 + 1) + c2.y;
        float m0 = -3.4e38f, m1 = -3.4e38f;
#pragma unroll
        for (int p=0;p<4;p++) {
            float2 v = up2(acc[op][p]);
            m0 = fmaxf(m0, v.x); m1 = fmaxf(m1, v.y);
        }
        m0 += bt0; m1 += bt1;
        m0 = fmaxf(m0, __shfl_xor_sync(0xffffffffu, m0, 1));
        m0 = fmaxf(m0, __shfl_xor_sync(0xffffffffu, m0, 2));
        m1 = fmaxf(m1, __shfl_xor_sync(0xffffffffu, m1, 1));
        m1 = fmaxf(m1, __shfl_xor_sync(0xffffffffu, m1, 2));
        if ((pg & 3) == 0) {
            outp[((long long)b*128 + o0    )*NPTS + nb + nl] = m0;
            outp[((long long)b*128 + o0 + 1)*NPTS + nb + nl] = m1;
        }
    }
}

// =====================================================================
extern "C" void kernel_launch(void* const* d_in, const int* in_sizes, int n_in,
                              void* d_out, int out_size)
{
    const float* xyz     = (const float*)d_in[0];
    const float* p1_sc_w = (const float*)d_in[1];
    const float* p1_sc_b = (const float*)d_in[2];
    const float* p1_a_w  = (const float*)d_in[3];
    const float* p1_a_b  = (const float*)d_in[4];
    const float* p1_b_w  = (const float*)d_in[5];
    const float* p1_b_b  = (const float*)d_in[6];
    const float* p1_c_w  = (const float*)d_in[7];
    const float* p1_c_b  = (const float*)d_in[8];
    const float* p2_sc_w = (const float*)d_in[9];
    const float* p2_sc_b = (const float*)d_in[10];
    const float* p2_a_w  = (const float*)d_in[11];
    const float* p2_a_b  = (const float*)d_in[12];
    const float* p2_b_w  = (const float*)d_in[13];
    const float* p2_b_b  = (const float*)d_in[14];
    const float* p2_c_w  = (const float*)d_in[15];
    const float* p2_c_b  = (const float*)d_in[16];
    float* outp = (float*)d_out;

    cudaFuncSetAttribute(stage1_kernel, cudaFuncAttributeMaxDynamicSharedMemorySize,
                         S1_FLOATS*4);
    cudaFuncSetAttribute(stage2_kernel, cudaFuncAttributeMaxDynamicSharedMemorySize,
                         T2_FLOATS*4);

    knn_part<<<512, 128, 32768>>>(xyz);
    knn_merge<<<NQ/256, 256>>>();
    stage1_kernel<<<NPOS/64, 128, S1_FLOATS*4>>>(
        xyz, p1_sc_w, p1_sc_b, p1_a_w, p1_a_b, p1_b_w, p1_b_b, p1_c_w, p1_c_b);
    stage2_kernel<<<NPOS/128, 256, T2_FLOATS*4>>>(
        p2_sc_w, p2_sc_b, p2_a_w, p2_a_b, p2_b_w, p2_b_b, p2_c_w, p2_c_b, outp);
}